// round 1
// baseline (speedup 1.0000x reference)
#include <cuda_runtime.h>
#include <cstdint>
#include <math.h>

// Problem constants (shapes fixed by setup_inputs)
#define DIN  768
#define DHID 256
#define NREL 2
#define MAXN 50000
#define MAXE 800000

// ---------------- scratch (device globals; no allocation allowed) -------------
__device__ float g_H1[(size_t)MAXN * DIN];    // fc1 output [N,768]
__device__ float g_T [(size_t)MAXN * 768];    // per-layer transforms [N, 256*3] (root|W0|W1)
__device__ float g_X [(size_t)MAXN * DHID];   // rgcn layer output [N,256]
__device__ float g_F [(size_t)MAXN * DHID];   // fc2 output [N,256]
__device__ float g_ACC[(size_t)MAXN * DHID * NREL]; // scatter accumulator [N, 2, 256]
__device__ int   g_CNT[MAXN * NREL];
__device__ int   g_flag[1];                   // 1 => edge indices are int64

// ---------------- dtype probe -------------------------------------------------
__global__ void probe_kernel(const long long* __restrict__ ei, long long Nn) {
    if (blockIdx.x == 0 && threadIdx.x == 0) {
        int ok = 1;
        for (int i = 0; i < 16; i++) {
            long long v = ei[i];
            if (v < 0 || v >= Nn) ok = 0;
        }
        g_flag[0] = ok;
    }
}

// ---------------- zero helpers ------------------------------------------------
__global__ void zero_f4_kernel(float4* __restrict__ p, long long n4) {
    long long i = (long long)blockIdx.x * blockDim.x + threadIdx.x;
    if (i < n4) p[i] = make_float4(0.f, 0.f, 0.f, 0.f);
}
__global__ void zero_i_kernel(int* __restrict__ p, int n) {
    int i = blockIdx.x * blockDim.x + threadIdx.x;
    if (i < n) p[i] = 0;
}

// ---------------- edge count --------------------------------------------------
__global__ void count_kernel(const int* __restrict__ ei32, const long long* __restrict__ ei64,
                             const int* __restrict__ et32, const long long* __restrict__ et64,
                             int* __restrict__ cnt, int E) {
    int e = blockIdx.x * blockDim.x + threadIdx.x;
    if (e >= E) return;
    long long dst; int r;
    if (g_flag[0]) { dst = ei64[(long long)E + e]; r = (int)et64[e]; }
    else           { dst = ei32[E + e];            r = et32[e]; }
    atomicAdd(&cnt[(int)dst * NREL + r], 1);
}

// ---------------- edge gather + vector-red scatter ---------------------------
__device__ __forceinline__ void red_add_v4(float* addr, float4 v) {
    asm volatile("red.global.add.v4.f32 [%0], {%1, %2, %3, %4};"
                 :: "l"(addr), "f"(v.x), "f"(v.y), "f"(v.z), "f"(v.w) : "memory");
}

__global__ void scatter_kernel(const int* __restrict__ ei32, const long long* __restrict__ ei64,
                               const int* __restrict__ et32, const long long* __restrict__ et64,
                               const float* __restrict__ T, float* __restrict__ ACC, int E) {
    int w = (blockIdx.x * blockDim.x + threadIdx.x) >> 5;
    int lane = threadIdx.x & 31;
    if (w >= E) return;
    long long src, dst; int r;
    if (g_flag[0]) { src = ei64[w]; dst = ei64[(long long)E + w]; r = (int)et64[w]; }
    else           { src = ei32[w]; dst = ei32[E + w];            r = et32[w]; }
    // transformed row for relation r lives in T columns [256 + r*256, 256 + (r+1)*256)
    const float4* Tp = (const float4*)(T + src * 768 + DHID + (long long)r * DHID);
    float* Ap = ACC + dst * (DHID * NREL) + (long long)r * DHID;
    float4 v0 = Tp[lane];
    float4 v1 = Tp[lane + 32];
    red_add_v4(Ap + lane * 4,        v0);
    red_add_v4(Ap + (lane + 32) * 4, v1);
}

// ---------------- mean-normalize: X = T[:, :256] + ACC_r0/cnt0 + ACC_r1/cnt1 --
__global__ void normalize_kernel(const float* __restrict__ T, const float* __restrict__ ACC,
                                 const int* __restrict__ cnt, float* __restrict__ X, int Nn) {
    long long idx = (long long)blockIdx.x * blockDim.x + threadIdx.x;
    if (idx >= (long long)Nn * 64) return;
    long long node = idx >> 6;
    int c4 = (int)(idx & 63);
    int c0 = cnt[node * 2], c1 = cnt[node * 2 + 1];
    float inv0 = 1.0f / (float)(c0 > 1 ? c0 : 1);
    float inv1 = 1.0f / (float)(c1 > 1 ? c1 : 1);
    float4 t  = ((const float4*)(T + node * 768))[c4];
    float4 a0 = ((const float4*)(ACC + node * 512))[c4];
    float4 a1 = ((const float4*)(ACC + node * 512))[c4 + 64];
    float4 o;
    o.x = t.x + a0.x * inv0 + a1.x * inv1;
    o.y = t.y + a0.y * inv0 + a1.y * inv1;
    o.z = t.z + a0.z * inv0 + a1.z * inv1;
    o.w = t.w + a0.w * inv0 + a1.w * inv1;
    ((float4*)(X + node * DHID))[c4] = o;
}

// ---------------- SGEMM: C[M,N] = A[M,K] @ B[K,N] (+bias)(+leaky) -------------
#define BM 128
#define BN 128
#define BK 8
#define TM 8
#define TN 8

template<int EPI>  // 0=none, 1=+bias, 2=+bias+leakyrelu(0.01)
__global__ __launch_bounds__(256)
void sgemm_kernel(const float* __restrict__ A, const float* __restrict__ B,
                  float* __restrict__ C, const float* __restrict__ bias,
                  int M, int N, int K, int lda, int ldb, int ldc) {
    __shared__ float As[BK][BM];
    __shared__ float Bs[BK][BN];

    int tid  = threadIdx.x;
    int row0 = blockIdx.y * BM;
    int col0 = blockIdx.x * BN;

    int arow = tid >> 1;          // 0..127
    int ak   = (tid & 1) * 4;     // 0 or 4
    int brow = tid >> 5;          // 0..7
    int bcol = (tid & 31) * 4;    // 0..124

    int tx = tid & 15, ty = tid >> 4;

    float acc[TM][TN];
    #pragma unroll
    for (int i = 0; i < TM; i++)
        #pragma unroll
        for (int j = 0; j < TN; j++) acc[i][j] = 0.f;

    bool arow_ok = (row0 + arow) < M;
    const float* Aptr = A + (long long)(row0 + arow) * lda + ak;
    const float* Bptr = B + (long long)brow * ldb + col0 + bcol;

    for (int k0 = 0; k0 < K; k0 += BK) {
        float4 av = arow_ok ? *(const float4*)(Aptr + k0) : make_float4(0.f, 0.f, 0.f, 0.f);
        As[ak + 0][arow] = av.x;
        As[ak + 1][arow] = av.y;
        As[ak + 2][arow] = av.z;
        As[ak + 3][arow] = av.w;
        *(float4*)&Bs[brow][bcol] = *(const float4*)(Bptr + (long long)k0 * ldb);
        __syncthreads();
        #pragma unroll
        for (int kk = 0; kk < BK; kk++) {
            float4 a0 = *(const float4*)&As[kk][ty * TM];
            float4 a1 = *(const float4*)&As[kk][ty * TM + 4];
            float4 b0 = *(const float4*)&Bs[kk][tx * TN];
            float4 b1 = *(const float4*)&Bs[kk][tx * TN + 4];
            float a[TM] = {a0.x, a0.y, a0.z, a0.w, a1.x, a1.y, a1.z, a1.w};
            float b[TN] = {b0.x, b0.y, b0.z, b0.w, b1.x, b1.y, b1.z, b1.w};
            #pragma unroll
            for (int i = 0; i < TM; i++)
                #pragma unroll
                for (int j = 0; j < TN; j++) acc[i][j] += a[i] * b[j];
        }
        __syncthreads();
    }

    #pragma unroll
    for (int i = 0; i < TM; i++) {
        int r = row0 + ty * TM + i;
        if (r >= M) continue;
        #pragma unroll
        for (int j = 0; j < TN; j += 4) {
            int c = col0 + tx * TN + j;
            float4 v = make_float4(acc[i][j], acc[i][j + 1], acc[i][j + 2], acc[i][j + 3]);
            if (EPI >= 1) {
                v.x += bias[c]; v.y += bias[c + 1]; v.z += bias[c + 2]; v.w += bias[c + 3];
            }
            if (EPI == 2) {
                v.x = v.x >= 0.f ? v.x : 0.01f * v.x;
                v.y = v.y >= 0.f ? v.y : 0.01f * v.y;
                v.z = v.z >= 0.f ? v.z : 0.01f * v.z;
                v.w = v.w >= 0.f ? v.w : 0.01f * v.w;
            }
            *(float4*)(C + (long long)r * ldc + c) = v;
        }
    }
}

// ---------------- final head: logits [256]->[2], softmax ----------------------
__global__ void head_kernel(const float* __restrict__ H, const float* __restrict__ W,
                            const float* __restrict__ b, float* __restrict__ out, int Nn) {
    int w = (blockIdx.x * blockDim.x + threadIdx.x) >> 5;
    int lane = threadIdx.x & 31;
    if (w >= Nn) return;
    const float4* h = (const float4*)(H + (long long)w * DHID);
    float d0 = 0.f, d1 = 0.f;
    #pragma unroll
    for (int q = 0; q < 2; q++) {
        float4 hv = h[lane * 2 + q];
        int kbase = lane * 8 + q * 4;
        // W row-major [256,2]: pairs (W[k][0],W[k][1])
        float4 w01 = ((const float4*)W)[kbase / 2];       // k, k+1
        float4 w23 = ((const float4*)W)[kbase / 2 + 1];   // k+2, k+3
        d0 += hv.x * w01.x + hv.y * w01.z + hv.z * w23.x + hv.w * w23.z;
        d1 += hv.x * w01.y + hv.y * w01.w + hv.z * w23.y + hv.w * w23.w;
    }
    #pragma unroll
    for (int off = 16; off > 0; off >>= 1) {
        d0 += __shfl_xor_sync(0xffffffffu, d0, off);
        d1 += __shfl_xor_sync(0xffffffffu, d1, off);
    }
    if (lane == 0) {
        d0 += b[0]; d1 += b[1];
        float m = fmaxf(d0, d1);
        float e0 = expf(d0 - m), e1 = expf(d1 - m);
        float s = e0 + e1;
        out[(long long)w * 2]     = e0 / s;
        out[(long long)w * 2 + 1] = e1 / s;
    }
}

// ---------------- launch ------------------------------------------------------
extern "C" void kernel_launch(void* const* d_in, const int* in_sizes, int n_in,
                              void* d_out, int out_size) {
    const float*     x     = (const float*)d_in[0];
    const void*      ei    = d_in[1];
    const void*      et    = d_in[3];
    const float* fc1_W = (const float*)d_in[4];
    const float* fc1_b = (const float*)d_in[5];
    const float* r1_w  = (const float*)d_in[6];   // [2,768,256]
    const float* r1_rt = (const float*)d_in[7];   // [768,256]
    const float* r1_b  = (const float*)d_in[8];
    const float* r2_w  = (const float*)d_in[9];   // [2,256,256]
    const float* r2_rt = (const float*)d_in[10];
    const float* r2_b  = (const float*)d_in[11];
    const float* fc2_W = (const float*)d_in[12];
    const float* fc2_b = (const float*)d_in[13];
    const float* out_W = (const float*)d_in[14];
    const float* out_b = (const float*)d_in[15];

    int Nn = in_sizes[0] / DIN;   // 50000
    int E  = in_sizes[3];         // 800000 (element count of edge_type)

    float *H1, *T, *X, *F, *ACC;  int *CNT;
    cudaGetSymbolAddress((void**)&H1,  g_H1);
    cudaGetSymbolAddress((void**)&T,   g_T);
    cudaGetSymbolAddress((void**)&X,   g_X);
    cudaGetSymbolAddress((void**)&F,   g_F);
    cudaGetSymbolAddress((void**)&ACC, g_ACC);
    cudaGetSymbolAddress((void**)&CNT, g_CNT);

    const int*       ei32 = (const int*)ei;
    const long long* ei64 = (const long long*)ei;
    const int*       et32 = (const int*)et;
    const long long* et64 = (const long long*)et;

    // dtype probe + counts (counts identical for both layers)
    probe_kernel<<<1, 32>>>(ei64, (long long)Nn);
    zero_i_kernel<<<(Nn * NREL + 255) / 256, 256>>>(CNT, Nn * NREL);
    count_kernel<<<(E + 255) / 256, 256>>>(ei32, ei64, et32, et64, CNT, E);

    // fc1 + leaky
    {
        dim3 grid((DIN + BN - 1) / BN, (Nn + BM - 1) / BM);
        sgemm_kernel<2><<<grid, 256>>>(x, fc1_W, H1, fc1_b, Nn, DIN, DIN, DIN, DIN, DIN);
    }

    dim3 gridH((DHID + BN - 1) / BN, (Nn + BM - 1) / BM);  // N=256 tiles

    // --- RGCN layer 1: T = [H1@root (+b) | H1@W0 | H1@W1], ldc=768 ---
    sgemm_kernel<1><<<gridH, 256>>>(H1, r1_rt,            T,       r1_b,   Nn, DHID, DIN, DIN, DHID, 768);
    sgemm_kernel<0><<<gridH, 256>>>(H1, r1_w,             T + 256, nullptr, Nn, DHID, DIN, DIN, DHID, 768);
    sgemm_kernel<0><<<gridH, 256>>>(H1, r1_w + DIN * DHID, T + 512, nullptr, Nn, DHID, DIN, DIN, DHID, 768);

    long long acc4 = (long long)Nn * 512 / 4;
    zero_f4_kernel<<<(unsigned)((acc4 + 255) / 256), 256>>>((float4*)ACC, acc4);
    scatter_kernel<<<(E + 7) / 8, 256>>>(ei32, ei64, et32, et64, T, ACC, E);
    normalize_kernel<<<(Nn * 64 + 255) / 256, 256>>>(T, ACC, CNT, X, Nn);

    // --- RGCN layer 2: T = [X@root (+b) | X@W0 | X@W1] ---
    sgemm_kernel<1><<<gridH, 256>>>(X, r2_rt,              T,       r2_b,   Nn, DHID, DHID, DHID, DHID, 768);
    sgemm_kernel<0><<<gridH, 256>>>(X, r2_w,               T + 256, nullptr, Nn, DHID, DHID, DHID, DHID, 768);
    sgemm_kernel<0><<<gridH, 256>>>(X, r2_w + DHID * DHID, T + 512, nullptr, Nn, DHID, DHID, DHID, DHID, 768);

    zero_f4_kernel<<<(unsigned)((acc4 + 255) / 256), 256>>>((float4*)ACC, acc4);
    scatter_kernel<<<(E + 7) / 8, 256>>>(ei32, ei64, et32, et64, T, ACC, E);
    normalize_kernel<<<(Nn * 64 + 255) / 256, 256>>>(T, ACC, CNT, X, Nn);

    // fc2 + leaky
    sgemm_kernel<2><<<gridH, 256>>>(X, fc2_W, F, fc2_b, Nn, DHID, DHID, DHID, DHID, DHID);

    // head + softmax
    head_kernel<<<(Nn + 7) / 8, 256>>>(F, out_W, out_b, (float*)d_out, Nn);
}

// round 4
// speedup vs baseline: 2.4266x; 2.4266x over previous
#include <cuda_runtime.h>
#include <cstdint>
#include <math.h>

#define DIN  768
#define DHID 256
#define NREL 2
#define MAXN 50000
#define MAXE 800000

// ---------------- scratch (device globals) ------------------------------------
__device__ float g_H1[(size_t)MAXN * DIN];    // fc1 output [N,768]
__device__ float g_T [(size_t)MAXN * 768];    // transforms [N, 256*3] (root|W0|W1)
__device__ float g_X [(size_t)MAXN * DHID];   // rgcn layer output [N,256]
__device__ float g_F [(size_t)MAXN * DHID];   // fc2 output [N,256]
__device__ float g_ACC[(size_t)MAXN * DHID * NREL]; // scatter accumulator [N,2,256]
__device__ int   g_CNT[MAXN * NREL];
__device__ int   g_flag[1];

// ---------------- tf32 helpers ------------------------------------------------
__device__ __forceinline__ float tf32r(float f) {
    uint32_t r;
    asm("cvt.rna.tf32.f32 %0, %1;" : "=r"(r) : "f"(f));
    return __uint_as_float(r);
}
__device__ __forceinline__ void mma1688(float* c, const uint32_t* a, const uint32_t* b) {
    asm volatile("mma.sync.aligned.m16n8k8.row.col.f32.tf32.tf32.f32 "
                 "{%0,%1,%2,%3}, {%4,%5,%6,%7}, {%8,%9}, {%0,%1,%2,%3};"
                 : "+f"(c[0]), "+f"(c[1]), "+f"(c[2]), "+f"(c[3])
                 : "r"(a[0]), "r"(a[1]), "r"(a[2]), "r"(a[3]), "r"(b[0]), "r"(b[1]));
}

// ---------------- tf32 mma.sync GEMM: C[M,N] = A[M,K] @ B[K,N] -----------------
// Block 128x128, BK=16, 8 warps (2x4), warp tile 64x32, double-buffered SMEM.
// grid = (ceil(M/128), N/128), block = 256. B is row-major [K,N] (ldb), no transpose.
#define APAD 20     // A row stride in floats (BK=16 + 4)
#define BPAD 136    // B row stride in floats (BN=128 + 8)

template<int EPI>  // 0=none, 1=+bias, 2=+bias+leakyrelu(0.01)
__global__ void __launch_bounds__(256, 2)
mma_gemm_kernel(const float* __restrict__ A, const float* __restrict__ B,
                float* __restrict__ C, const float* __restrict__ bias,
                int M, int K, int ldb, int ldc) {
    __shared__ float As[2][128][APAD];
    __shared__ float Bs[2][16][BPAD];

    const int tid  = threadIdx.x;
    const int w    = tid >> 5;
    const int lane = tid & 31;
    const int g    = lane >> 2;      // 0..7
    const int cq   = lane & 3;       // 0..3
    const int wm   = w >> 2;         // 0..1
    const int wn   = w & 3;          // 0..3
    const int row0 = blockIdx.x * 128;
    const int col0 = blockIdx.y * 128;

    float acc[4][4][4];
    #pragma unroll
    for (int mi = 0; mi < 4; mi++)
        #pragma unroll
        for (int ni = 0; ni < 4; ni++)
            #pragma unroll
            for (int q = 0; q < 4; q++) acc[mi][ni][q] = 0.f;

    const int nk = K >> 4;
    float4 ra[2], rb[2];

    auto loadA = [&](int k0, float4* r) {
        #pragma unroll
        for (int it = 0; it < 2; it++) {
            int idx = tid + it * 256;           // 0..511
            int row = idx >> 2, c4 = idx & 3;
            int gr = row0 + row;
            float4 v = make_float4(0.f, 0.f, 0.f, 0.f);
            if (gr < M) v = *(const float4*)(A + (size_t)gr * K + k0 + c4 * 4);
            r[it] = v;
        }
    };
    auto loadB = [&](int k0, float4* r) {
        #pragma unroll
        for (int it = 0; it < 2; it++) {
            int idx = tid + it * 256;
            int row = idx >> 5, c4 = idx & 31;
            r[it] = *(const float4*)(B + (size_t)(k0 + row) * ldb + col0 + c4 * 4);
        }
    };
    auto storeA = [&](int s, const float4* r) {
        #pragma unroll
        for (int it = 0; it < 2; it++) {
            int idx = tid + it * 256;
            int row = idx >> 2, c4 = idx & 3;
            float4 v = r[it];
            v.x = tf32r(v.x); v.y = tf32r(v.y); v.z = tf32r(v.z); v.w = tf32r(v.w);
            *(float4*)&As[s][row][c4 * 4] = v;
        }
    };
    auto storeB = [&](int s, const float4* r) {
        #pragma unroll
        for (int it = 0; it < 2; it++) {
            int idx = tid + it * 256;
            int row = idx >> 5, c4 = idx & 31;
            float4 v = r[it];
            v.x = tf32r(v.x); v.y = tf32r(v.y); v.z = tf32r(v.z); v.w = tf32r(v.w);
            *(float4*)&Bs[s][row][c4 * 4] = v;
        }
    };

    loadA(0, ra); loadB(0, rb);
    storeA(0, ra); storeB(0, rb);
    __syncthreads();

    for (int t = 0; t < nk; t++) {
        const int cur = t & 1;
        if (t + 1 < nk) { loadA((t + 1) << 4, ra); loadB((t + 1) << 4, rb); }

        #pragma unroll
        for (int k8 = 0; k8 < 2; k8++) {
            const int kc = k8 * 8 + cq;
            uint32_t af[4][4];
            #pragma unroll
            for (int mi = 0; mi < 4; mi++) {
                int rb_ = wm * 64 + mi * 16;
                af[mi][0] = __float_as_uint(As[cur][rb_ + g][kc]);
                af[mi][1] = __float_as_uint(As[cur][rb_ + g + 8][kc]);
                af[mi][2] = __float_as_uint(As[cur][rb_ + g][kc + 4]);
                af[mi][3] = __float_as_uint(As[cur][rb_ + g + 8][kc + 4]);
            }
            uint32_t bf[4][2];
            #pragma unroll
            for (int ni = 0; ni < 4; ni++) {
                int cb = wn * 32 + ni * 8 + g;
                bf[ni][0] = __float_as_uint(Bs[cur][k8 * 8 + cq][cb]);
                bf[ni][1] = __float_as_uint(Bs[cur][k8 * 8 + cq + 4][cb]);
            }
            #pragma unroll
            for (int mi = 0; mi < 4; mi++)
                #pragma unroll
                for (int ni = 0; ni < 4; ni++)
                    mma1688(acc[mi][ni], af[mi], bf[ni]);
        }

        if (t + 1 < nk) { storeA(cur ^ 1, ra); storeB(cur ^ 1, rb); }
        __syncthreads();
    }

    // ---- epilogue ----
    #pragma unroll
    for (int mi = 0; mi < 4; mi++) {
        int rbase = row0 + wm * 64 + mi * 16;
        int r0 = rbase + g, r1 = rbase + g + 8;
        #pragma unroll
        for (int ni = 0; ni < 4; ni++) {
            int cl = wn * 32 + ni * 8 + cq * 2;   // column within block tile
            int col = col0 + cl;                  // global column
            float b0 = 0.f, b1 = 0.f;
            if (EPI >= 1) { b0 = bias[col]; b1 = bias[col + 1]; }
            float v0 = acc[mi][ni][0] + b0, v1 = acc[mi][ni][1] + b1;
            float v2 = acc[mi][ni][2] + b0, v3 = acc[mi][ni][3] + b1;
            if (EPI == 2) {
                v0 = v0 >= 0.f ? v0 : 0.01f * v0;
                v1 = v1 >= 0.f ? v1 : 0.01f * v1;
                v2 = v2 >= 0.f ? v2 : 0.01f * v2;
                v3 = v3 >= 0.f ? v3 : 0.01f * v3;
            }
            if (r0 < M) *(float2*)(C + (size_t)r0 * ldc + col) = make_float2(v0, v1);
            if (r1 < M) *(float2*)(C + (size_t)r1 * ldc + col) = make_float2(v2, v3);
        }
    }
}

// ---------------- edge machinery (validated in R1) ----------------------------
__global__ void probe_kernel(const long long* __restrict__ ei, long long Nn) {
    if (blockIdx.x == 0 && threadIdx.x == 0) {
        int ok = 1;
        for (int i = 0; i < 16; i++) {
            long long v = ei[i];
            if (v < 0 || v >= Nn) ok = 0;
        }
        g_flag[0] = ok;
    }
}
__global__ void zero_f4_kernel(float4* __restrict__ p, long long n4) {
    long long i = (long long)blockIdx.x * blockDim.x + threadIdx.x;
    if (i < n4) p[i] = make_float4(0.f, 0.f, 0.f, 0.f);
}
__global__ void zero_i_kernel(int* __restrict__ p, int n) {
    int i = blockIdx.x * blockDim.x + threadIdx.x;
    if (i < n) p[i] = 0;
}
__global__ void count_kernel(const int* __restrict__ ei32, const long long* __restrict__ ei64,
                             const int* __restrict__ et32, const long long* __restrict__ et64,
                             int* __restrict__ cnt, int E) {
    int e = blockIdx.x * blockDim.x + threadIdx.x;
    if (e >= E) return;
    long long dst; int r;
    if (g_flag[0]) { dst = ei64[(long long)E + e]; r = (int)et64[e]; }
    else           { dst = ei32[E + e];            r = et32[e]; }
    atomicAdd(&cnt[(int)dst * NREL + r], 1);
}
__device__ __forceinline__ void red_add_v4(float* addr, float4 v) {
    asm volatile("red.global.add.v4.f32 [%0], {%1, %2, %3, %4};"
                 :: "l"(addr), "f"(v.x), "f"(v.y), "f"(v.z), "f"(v.w) : "memory");
}
__global__ void scatter_kernel(const int* __restrict__ ei32, const long long* __restrict__ ei64,
                               const int* __restrict__ et32, const long long* __restrict__ et64,
                               const float* __restrict__ T, float* __restrict__ ACC, int E) {
    int w = (blockIdx.x * blockDim.x + threadIdx.x) >> 5;
    int lane = threadIdx.x & 31;
    if (w >= E) return;
    long long src, dst; int r;
    if (g_flag[0]) { src = ei64[w]; dst = ei64[(long long)E + w]; r = (int)et64[w]; }
    else           { src = ei32[w]; dst = ei32[E + w];            r = et32[w]; }
    const float4* Tp = (const float4*)(T + src * 768 + DHID + (long long)r * DHID);
    float* Ap = ACC + dst * (DHID * NREL) + (long long)r * DHID;
    float4 v0 = Tp[lane];
    float4 v1 = Tp[lane + 32];
    red_add_v4(Ap + lane * 4,        v0);
    red_add_v4(Ap + (lane + 32) * 4, v1);
}
__global__ void normalize_kernel(const float* __restrict__ T, const float* __restrict__ ACC,
                                 const int* __restrict__ cnt, float* __restrict__ X, int Nn) {
    long long idx = (long long)blockIdx.x * blockDim.x + threadIdx.x;
    if (idx >= (long long)Nn * 64) return;
    long long node = idx >> 6;
    int c4 = (int)(idx & 63);
    int c0 = cnt[node * 2], c1 = cnt[node * 2 + 1];
    float inv0 = 1.0f / (float)(c0 > 1 ? c0 : 1);
    float inv1 = 1.0f / (float)(c1 > 1 ? c1 : 1);
    float4 t  = ((const float4*)(T + node * 768))[c4];
    float4 a0 = ((const float4*)(ACC + node * 512))[c4];
    float4 a1 = ((const float4*)(ACC + node * 512))[c4 + 64];
    float4 o;
    o.x = t.x + a0.x * inv0 + a1.x * inv1;
    o.y = t.y + a0.y * inv0 + a1.y * inv1;
    o.z = t.z + a0.z * inv0 + a1.z * inv1;
    o.w = t.w + a0.w * inv0 + a1.w * inv1;
    ((float4*)(X + node * DHID))[c4] = o;
}
__global__ void head_kernel(const float* __restrict__ H, const float* __restrict__ W,
                            const float* __restrict__ b, float* __restrict__ out, int Nn) {
    int w = (blockIdx.x * blockDim.x + threadIdx.x) >> 5;
    int lane = threadIdx.x & 31;
    if (w >= Nn) return;
    const float4* h = (const float4*)(H + (long long)w * DHID);
    float d0 = 0.f, d1 = 0.f;
    #pragma unroll
    for (int q = 0; q < 2; q++) {
        float4 hv = h[lane * 2 + q];
        int kbase = lane * 8 + q * 4;
        float4 w01 = ((const float4*)W)[kbase / 2];
        float4 w23 = ((const float4*)W)[kbase / 2 + 1];
        d0 += hv.x * w01.x + hv.y * w01.z + hv.z * w23.x + hv.w * w23.z;
        d1 += hv.x * w01.y + hv.y * w01.w + hv.z * w23.y + hv.w * w23.w;
    }
    #pragma unroll
    for (int off = 16; off > 0; off >>= 1) {
        d0 += __shfl_xor_sync(0xffffffffu, d0, off);
        d1 += __shfl_xor_sync(0xffffffffu, d1, off);
    }
    if (lane == 0) {
        d0 += b[0]; d1 += b[1];
        float m = fmaxf(d0, d1);
        float e0 = expf(d0 - m), e1 = expf(d1 - m);
        float s = e0 + e1;
        out[(long long)w * 2]     = e0 / s;
        out[(long long)w * 2 + 1] = e1 / s;
    }
}

// ---------------- launch ------------------------------------------------------
extern "C" void kernel_launch(void* const* d_in, const int* in_sizes, int n_in,
                              void* d_out, int out_size) {
    const float* x     = (const float*)d_in[0];
    const void*  ei    = d_in[1];
    const void*  et    = d_in[3];
    const float* fc1_W = (const float*)d_in[4];
    const float* fc1_b = (const float*)d_in[5];
    const float* r1_w  = (const float*)d_in[6];   // [2,768,256]
    const float* r1_rt = (const float*)d_in[7];   // [768,256]
    const float* r1_b  = (const float*)d_in[8];
    const float* r2_w  = (const float*)d_in[9];   // [2,256,256]
    const float* r2_rt = (const float*)d_in[10];
    const float* r2_b  = (const float*)d_in[11];
    const float* fc2_W = (const float*)d_in[12];
    const float* fc2_b = (const float*)d_in[13];
    const float* out_W = (const float*)d_in[14];
    const float* out_b = (const float*)d_in[15];

    int Nn = in_sizes[0] / DIN;   // 50000
    int E  = in_sizes[3];         // 800000

    float *H1, *T, *X, *F, *ACC;  int *CNT;
    cudaGetSymbolAddress((void**)&H1,  g_H1);
    cudaGetSymbolAddress((void**)&T,   g_T);
    cudaGetSymbolAddress((void**)&X,   g_X);
    cudaGetSymbolAddress((void**)&F,   g_F);
    cudaGetSymbolAddress((void**)&ACC, g_ACC);
    cudaGetSymbolAddress((void**)&CNT, g_CNT);

    const int*       ei32 = (const int*)ei;
    const long long* ei64 = (const long long*)ei;
    const int*       et32 = (const int*)et;
    const long long* et64 = (const long long*)et;

    probe_kernel<<<1, 32>>>(ei64, (long long)Nn);
    zero_i_kernel<<<(Nn * NREL + 255) / 256, 256>>>(CNT, Nn * NREL);
    count_kernel<<<(E + 255) / 256, 256>>>(ei32, ei64, et32, et64, CNT, E);

    int mb = (Nn + 127) / 128;            // 391
    long long acc4 = (long long)Nn * 512 / 4;

    // ---- fc1: H1 = leaky(x @ fc1_W + fc1_b)  [K=768, N=768] ----
    mma_gemm_kernel<2><<<dim3(mb, 6), 256>>>(x, fc1_W, H1, fc1_b, Nn, DIN, DIN, DIN);

    // ---- layer-1 transforms into T (ldc=768): root(+b) | W0 | W1  [K=768,N=256] ----
    mma_gemm_kernel<1><<<dim3(mb, 2), 256>>>(H1, r1_rt,             T,       r1_b,   Nn, DIN, DHID, 768);
    mma_gemm_kernel<0><<<dim3(mb, 2), 256>>>(H1, r1_w,              T + 256, nullptr, Nn, DIN, DHID, 768);
    mma_gemm_kernel<0><<<dim3(mb, 2), 256>>>(H1, r1_w + DIN * DHID, T + 512, nullptr, Nn, DIN, DHID, 768);

    zero_f4_kernel<<<(unsigned)((acc4 + 255) / 256), 256>>>((float4*)ACC, acc4);
    scatter_kernel<<<(E + 7) / 8, 256>>>(ei32, ei64, et32, et64, T, ACC, E);
    normalize_kernel<<<(Nn * 64 + 255) / 256, 256>>>(T, ACC, CNT, X, Nn);

    // ---- layer-2 transforms [K=256, N=256] ----
    mma_gemm_kernel<1><<<dim3(mb, 2), 256>>>(X, r2_rt,              T,       r2_b,   Nn, DHID, DHID, 768);
    mma_gemm_kernel<0><<<dim3(mb, 2), 256>>>(X, r2_w,               T + 256, nullptr, Nn, DHID, DHID, 768);
    mma_gemm_kernel<0><<<dim3(mb, 2), 256>>>(X, r2_w + DHID * DHID, T + 512, nullptr, Nn, DHID, DHID, 768);

    zero_f4_kernel<<<(unsigned)((acc4 + 255) / 256), 256>>>((float4*)ACC, acc4);
    scatter_kernel<<<(E + 7) / 8, 256>>>(ei32, ei64, et32, et64, T, ACC, E);
    normalize_kernel<<<(Nn * 64 + 255) / 256, 256>>>(T, ACC, CNT, X, Nn);

    // ---- fc2: F = leaky(X @ fc2_W + fc2_b)  [K=256, N=256] ----
    mma_gemm_kernel<2><<<dim3(mb, 2), 256>>>(X, fc2_W, F, fc2_b, Nn, DHID, DHID, DHID);

    // ---- head + softmax ----
    head_kernel<<<(Nn + 7) / 8, 256>>>(F, out_W, out_b, (float*)d_out, Nn);
}

// round 6
// speedup vs baseline: 2.6236x; 1.0812x over previous
#include <cuda_runtime.h>
#include <cstdint>
#include <math.h>

#define DIN  768
#define DHID 256
#define NREL 2
#define MAXN 50000
#define MAXE 800000

// ---------------- scratch (device globals) ------------------------------------
__device__ float g_H1[(size_t)MAXN * DIN];    // fc1 output [N,768] (tf32-rounded)
__device__ float g_T [(size_t)MAXN * 768];    // rounded x, then transforms [N,768]
__device__ float g_X [(size_t)MAXN * DHID];   // rgcn layer output [N,256] (rounded)
__device__ float g_F [(size_t)MAXN * DHID];   // fc2 output [N,256]
__device__ float g_ACC[(size_t)MAXN * DHID * NREL]; // scatter accumulator [N,2,256]
__device__ float g_RW[1441792];               // pre-rounded weights
__device__ int   g_CNT[MAXN * NREL];
__device__ int   g_flag[1];

// offsets into g_RW (floats)
#define OFF_FC1   0
#define OFF_R1RT  589824
#define OFF_R1W   786432        // both relations contiguous (2*768*256)
#define OFF_R2RT  1179648
#define OFF_R2W   1245184       // 2*256*256
#define OFF_FC2   1376256

// ---------------- tf32 helpers ------------------------------------------------
__device__ __forceinline__ float tf32r(float f) {
    uint32_t r;
    asm("cvt.rna.tf32.f32 %0, %1;" : "=r"(r) : "f"(f));
    return __uint_as_float(r);
}
__device__ __forceinline__ void mma1688(float* c, const uint32_t* a, const uint32_t* b) {
    asm volatile("mma.sync.aligned.m16n8k8.row.col.f32.tf32.tf32.f32 "
                 "{%0,%1,%2,%3}, {%4,%5,%6,%7}, {%8,%9}, {%0,%1,%2,%3};"
                 : "+f"(c[0]), "+f"(c[1]), "+f"(c[2]), "+f"(c[3])
                 : "r"(a[0]), "r"(a[1]), "r"(a[2]), "r"(a[3]), "r"(b[0]), "r"(b[1]));
}
__device__ __forceinline__ void cpasync16(uint32_t saddr, const void* gptr, uint32_t sz) {
    asm volatile("cp.async.ca.shared.global [%0], [%1], 16, %2;"
                 :: "r"(saddr), "l"(gptr), "r"(sz) : "memory");
}
__device__ __forceinline__ uint32_t smem_u32(const void* p) {
    uint32_t a;
    asm("{ .reg .u64 t; cvta.to.shared.u64 t, %1; cvt.u32.u64 %0, t; }" : "=r"(a) : "l"(p));
    return a;
}

// ---------------- tf32 mma.sync GEMM with cp.async 3-stage pipeline ------------
// C[M,N] = A[M,K] @ B[K,N]; block 128x128, BK=16, 8 warps (2x4), warp tile 64x32.
// A and B must already be tf32-rounded. B row-major [K,N].
#define APAD 20
#define BPAD 136
#define STAGES 3
#define ASZ (128 * APAD)
#define BSZ (16 * BPAD)
#define GEMM_SMEM (STAGES * (ASZ + BSZ) * 4)

template<int EPI, int RND>  // EPI: 0 none, 1 +bias, 2 +bias+leaky; RND: round output to tf32
__global__ void __launch_bounds__(256, 2)
mma_gemm_kernel(const float* __restrict__ A, const float* __restrict__ B,
                float* __restrict__ C, const float* __restrict__ bias,
                int M, int K, int ldb, int ldc) {
    extern __shared__ float sm[];
    const uint32_t smem_base = smem_u32(sm);

    const int tid  = threadIdx.x;
    const int w    = tid >> 5;
    const int lane = tid & 31;
    const int g    = lane >> 2;      // 0..7
    const int cq   = lane & 3;       // 0..3
    const int wm   = w >> 2;         // 0..1
    const int wn   = w & 3;          // 0..3
    const int row0 = blockIdx.x * 128;
    const int col0 = blockIdx.y * 128;

    // per-thread fill mapping (constant across stages)
    const int ar  = tid >> 2;            // A row 0..63 (+64 for 2nd chunk)
    const int ac4 = tid & 3;             // A 16B chunk in row
    const int br  = tid >> 5;            // B row 0..7 (+8)
    const int bc4 = tid & 31;            // B 16B chunk in row
    const uint32_t aoff0 = (uint32_t)(ar * APAD + ac4 * 4) * 4;
    const uint32_t aoff1 = aoff0 + (uint32_t)(64 * APAD) * 4;
    const uint32_t boff0 = (uint32_t)(br * BPAD + bc4 * 4) * 4;
    const uint32_t boff1 = boff0 + (uint32_t)(8 * BPAD) * 4;

    const int gr0 = row0 + ar, gr1 = row0 + ar + 64;
    const uint32_t sz0 = (gr0 < M) ? 16u : 0u;
    const uint32_t sz1 = (gr1 < M) ? 16u : 0u;
    const float* agp0 = A + (size_t)(gr0 < M ? gr0 : 0) * K + ac4 * 4;
    const float* agp1 = A + (size_t)(gr1 < M ? gr1 : 0) * K + ac4 * 4;
    const float* bgp0 = B + (size_t)br * ldb + col0 + bc4 * 4;
    const float* bgp1 = bgp0 + (size_t)8 * ldb;
    const size_t bstep = (size_t)16 * ldb;

    const int nk = K >> 4;

    auto issue_stage = [&](int s, int t) {
        uint32_t abase = smem_base + (uint32_t)(s * ASZ) * 4;
        uint32_t bbase = smem_base + (uint32_t)(STAGES * ASZ + s * BSZ) * 4;
        const float* ap0 = agp0 + t * 16;
        const float* ap1 = agp1 + t * 16;
        const float* bp0 = bgp0 + (size_t)t * bstep;
        const float* bp1 = bgp1 + (size_t)t * bstep;
        cpasync16(abase + aoff0, ap0, sz0);
        cpasync16(abase + aoff1, ap1, sz1);
        cpasync16(bbase + boff0, bp0, 16u);
        cpasync16(bbase + boff1, bp1, 16u);
        asm volatile("cp.async.commit_group;" ::: "memory");
    };

    float acc[4][4][4];
    #pragma unroll
    for (int mi = 0; mi < 4; mi++)
        #pragma unroll
        for (int ni = 0; ni < 4; ni++)
            #pragma unroll
            for (int q = 0; q < 4; q++) acc[mi][ni][q] = 0.f;

    issue_stage(0, 0);
    if (nk > 1) issue_stage(1, 1); else asm volatile("cp.async.commit_group;" ::: "memory");

    for (int t = 0; t < nk; t++) {
        if (t + 1 < nk) { asm volatile("cp.async.wait_group 1;" ::: "memory"); }
        else            { asm volatile("cp.async.wait_group 0;" ::: "memory"); }
        __syncthreads();
        if (t + 2 < nk) issue_stage((t + 2) % STAGES, t + 2);

        const int s = t % STAGES;
        const float* As_st = sm + s * ASZ;
        const float* Bs_st = sm + STAGES * ASZ + s * BSZ;
        const int cbb = wn * 32 + g;

        #pragma unroll
        for (int k8 = 0; k8 < 2; k8++) {
            const int kc = k8 * 8 + cq;
            uint32_t af[4][4];
            #pragma unroll
            for (int mi = 0; mi < 4; mi++) {
                const float* ap = As_st + (wm * 64 + mi * 16 + g) * APAD;
                af[mi][0] = __float_as_uint(ap[kc]);
                af[mi][1] = __float_as_uint(ap[8 * APAD + kc]);
                af[mi][2] = __float_as_uint(ap[kc + 4]);
                af[mi][3] = __float_as_uint(ap[8 * APAD + kc + 4]);
            }
            uint32_t bf[4][2];
            const float* bp0r = Bs_st + kc * BPAD + cbb;
            const float* bp1r = bp0r + 4 * BPAD;
            #pragma unroll
            for (int ni = 0; ni < 4; ni++) {
                bf[ni][0] = __float_as_uint(bp0r[ni * 8]);
                bf[ni][1] = __float_as_uint(bp1r[ni * 8]);
            }
            #pragma unroll
            for (int mi = 0; mi < 4; mi++)
                #pragma unroll
                for (int ni = 0; ni < 4; ni++)
                    mma1688(acc[mi][ni], af[mi], bf[ni]);
        }
        __syncthreads();
    }

    // ---- epilogue ----
    #pragma unroll
    for (int mi = 0; mi < 4; mi++) {
        int rbase = row0 + wm * 64 + mi * 16;
        int r0 = rbase + g, r1 = rbase + g + 8;
        #pragma unroll
        for (int ni = 0; ni < 4; ni++) {
            int col = col0 + wn * 32 + ni * 8 + cq * 2;
            float b0 = 0.f, b1 = 0.f;
            if (EPI >= 1) { b0 = bias[col]; b1 = bias[col + 1]; }
            float v0 = acc[mi][ni][0] + b0, v1 = acc[mi][ni][1] + b1;
            float v2 = acc[mi][ni][2] + b0, v3 = acc[mi][ni][3] + b1;
            if (EPI == 2) {
                v0 = v0 >= 0.f ? v0 : 0.01f * v0;
                v1 = v1 >= 0.f ? v1 : 0.01f * v1;
                v2 = v2 >= 0.f ? v2 : 0.01f * v2;
                v3 = v3 >= 0.f ? v3 : 0.01f * v3;
            }
            if (RND) {
                v0 = tf32r(v0); v1 = tf32r(v1); v2 = tf32r(v2); v3 = tf32r(v3);
            }
            if (r0 < M) *(float2*)(C + (size_t)r0 * ldc + col) = make_float2(v0, v1);
            if (r1 < M) *(float2*)(C + (size_t)r1 * ldc + col) = make_float2(v2, v3);
        }
    }
}

// ---------------- round-copy: dst = tf32(src) ---------------------------------
__global__ void round_copy_kernel(const float4* __restrict__ src, float4* __restrict__ dst,
                                  long long n4) {
    long long i = (long long)blockIdx.x * blockDim.x + threadIdx.x;
    if (i < n4) {
        float4 v = src[i];
        v.x = tf32r(v.x); v.y = tf32r(v.y); v.z = tf32r(v.z); v.w = tf32r(v.w);
        dst[i] = v;
    }
}

// ---------------- edge machinery ----------------------------------------------
__global__ void probe_kernel(const long long* __restrict__ ei, long long Nn) {
    if (blockIdx.x == 0 && threadIdx.x == 0) {
        int ok = 1;
        for (int i = 0; i < 16; i++) {
            long long v = ei[i];
            if (v < 0 || v >= Nn) ok = 0;
        }
        g_flag[0] = ok;
    }
}
__global__ void zero_f4_kernel(float4* __restrict__ p, long long n4) {
    long long i = (long long)blockIdx.x * blockDim.x + threadIdx.x;
    if (i < n4) p[i] = make_float4(0.f, 0.f, 0.f, 0.f);
}
__global__ void zero_i_kernel(int* __restrict__ p, int n) {
    int i = blockIdx.x * blockDim.x + threadIdx.x;
    if (i < n) p[i] = 0;
}
__global__ void count_kernel(const int* __restrict__ ei32, const long long* __restrict__ ei64,
                             const int* __restrict__ et32, const long long* __restrict__ et64,
                             int* __restrict__ cnt, int E) {
    int e = blockIdx.x * blockDim.x + threadIdx.x;
    if (e >= E) return;
    long long dst; int r;
    if (g_flag[0]) { dst = ei64[(long long)E + e]; r = (int)et64[e]; }
    else           { dst = ei32[E + e];            r = et32[e]; }
    atomicAdd(&cnt[(int)dst * NREL + r], 1);
}
__device__ __forceinline__ void red_add_v4(float* addr, float4 v) {
    asm volatile("red.global.add.v4.f32 [%0], {%1, %2, %3, %4};"
                 :: "l"(addr), "f"(v.x), "f"(v.y), "f"(v.z), "f"(v.w) : "memory");
}
__global__ void scatter_kernel(const int* __restrict__ ei32, const long long* __restrict__ ei64,
                               const int* __restrict__ et32, const long long* __restrict__ et64,
                               const float* __restrict__ T, float* __restrict__ ACC, int E) {
    int w = (blockIdx.x * blockDim.x + threadIdx.x) >> 5;
    int lane = threadIdx.x & 31;
    if (w >= E) return;
    long long src, dst; int r;
    if (g_flag[0]) { src = ei64[w]; dst = ei64[(long long)E + w]; r = (int)et64[w]; }
    else           { src = ei32[w]; dst = ei32[E + w];            r = et32[w]; }
    const float4* Tp = (const float4*)(T + src * 768 + DHID + (long long)r * DHID);
    float* Ap = ACC + dst * (DHID * NREL) + (long long)r * DHID;
    float4 v0 = Tp[lane];
    float4 v1 = Tp[lane + 32];
    red_add_v4(Ap + lane * 4,        v0);
    red_add_v4(Ap + (lane + 32) * 4, v1);
}
__global__ void normalize_kernel(const float* __restrict__ T, const float* __restrict__ ACC,
                                 const int* __restrict__ cnt, float* __restrict__ X, int Nn) {
    long long idx = (long long)blockIdx.x * blockDim.x + threadIdx.x;
    if (idx >= (long long)Nn * 64) return;
    long long node = idx >> 6;
    int c4 = (int)(idx & 63);
    int c0 = cnt[node * 2], c1 = cnt[node * 2 + 1];
    float inv0 = 1.0f / (float)(c0 > 1 ? c0 : 1);
    float inv1 = 1.0f / (float)(c1 > 1 ? c1 : 1);
    float4 t  = ((const float4*)(T + node * 768))[c4];
    float4 a0 = ((const float4*)(ACC + node * 512))[c4];
    float4 a1 = ((const float4*)(ACC + node * 512))[c4 + 64];
    float4 o;
    o.x = tf32r(t.x + a0.x * inv0 + a1.x * inv1);
    o.y = tf32r(t.y + a0.y * inv0 + a1.y * inv1);
    o.z = tf32r(t.z + a0.z * inv0 + a1.z * inv1);
    o.w = tf32r(t.w + a0.w * inv0 + a1.w * inv1);
    ((float4*)(X + node * DHID))[c4] = o;
}
__global__ void head_kernel(const float* __restrict__ H, const float* __restrict__ W,
                            const float* __restrict__ b, float* __restrict__ out, int Nn) {
    int w = (blockIdx.x * blockDim.x + threadIdx.x) >> 5;
    int lane = threadIdx.x & 31;
    if (w >= Nn) return;
    const float4* h = (const float4*)(H + (long long)w * DHID);
    float d0 = 0.f, d1 = 0.f;
    #pragma unroll
    for (int q = 0; q < 2; q++) {
        float4 hv = h[lane * 2 + q];
        int kbase = lane * 8 + q * 4;
        float4 w01 = ((const float4*)W)[kbase / 2];
        float4 w23 = ((const float4*)W)[kbase / 2 + 1];
        d0 += hv.x * w01.x + hv.y * w01.z + hv.z * w23.x + hv.w * w23.z;
        d1 += hv.x * w01.y + hv.y * w01.w + hv.z * w23.y + hv.w * w23.w;
    }
    #pragma unroll
    for (int off = 16; off > 0; off >>= 1) {
        d0 += __shfl_xor_sync(0xffffffffu, d0, off);
        d1 += __shfl_xor_sync(0xffffffffu, d1, off);
    }
    if (lane == 0) {
        d0 += b[0]; d1 += b[1];
        float m = fmaxf(d0, d1);
        float e0 = expf(d0 - m), e1 = expf(d1 - m);
        float s = e0 + e1;
        out[(long long)w * 2]     = e0 / s;
        out[(long long)w * 2 + 1] = e1 / s;
    }
}

// ---------------- launch ------------------------------------------------------
extern "C" void kernel_launch(void* const* d_in, const int* in_sizes, int n_in,
                              void* d_out, int out_size) {
    const float* x     = (const float*)d_in[0];
    const void*  ei    = d_in[1];
    const void*  et    = d_in[3];
    const float* fc1_W = (const float*)d_in[4];
    const float* fc1_b = (const float*)d_in[5];
    const float* r1_w  = (const float*)d_in[6];
    const float* r1_rt = (const float*)d_in[7];
    const float* r1_b  = (const float*)d_in[8];
    const float* r2_w  = (const float*)d_in[9];
    const float* r2_rt = (const float*)d_in[10];
    const float* r2_b  = (const float*)d_in[11];
    const float* fc2_W = (const float*)d_in[12];
    const float* fc2_b = (const float*)d_in[13];
    const float* out_W = (const float*)d_in[14];
    const float* out_b = (const float*)d_in[15];

    int Nn = in_sizes[0] / DIN;   // 50000
    int E  = in_sizes[3];         // 800000

    float *H1, *T, *X, *F, *ACC, *RW;  int *CNT;
    cudaGetSymbolAddress((void**)&H1,  g_H1);
    cudaGetSymbolAddress((void**)&T,   g_T);
    cudaGetSymbolAddress((void**)&X,   g_X);
    cudaGetSymbolAddress((void**)&F,   g_F);
    cudaGetSymbolAddress((void**)&ACC, g_ACC);
    cudaGetSymbolAddress((void**)&RW,  g_RW);
    cudaGetSymbolAddress((void**)&CNT, g_CNT);

    cudaFuncSetAttribute(mma_gemm_kernel<2, 1>, cudaFuncAttributeMaxDynamicSharedMemorySize, GEMM_SMEM);
    cudaFuncSetAttribute(mma_gemm_kernel<1, 0>, cudaFuncAttributeMaxDynamicSharedMemorySize, GEMM_SMEM);
    cudaFuncSetAttribute(mma_gemm_kernel<0, 0>, cudaFuncAttributeMaxDynamicSharedMemorySize, GEMM_SMEM);
    cudaFuncSetAttribute(mma_gemm_kernel<2, 0>, cudaFuncAttributeMaxDynamicSharedMemorySize, GEMM_SMEM);

    const int*       ei32 = (const int*)ei;
    const long long* ei64 = (const long long*)ei;
    const int*       et32 = (const int*)et;
    const long long* et64 = (const long long*)et;

    probe_kernel<<<1, 32>>>(ei64, (long long)Nn);
    zero_i_kernel<<<(Nn * NREL + 255) / 256, 256>>>(CNT, Nn * NREL);
    count_kernel<<<(E + 255) / 256, 256>>>(ei32, ei64, et32, et64, CNT, E);

    // pre-round x and weights to tf32
    long long x4 = (long long)Nn * DIN / 4;
    round_copy_kernel<<<(unsigned)((x4 + 255) / 256), 256>>>((const float4*)x, (float4*)T, x4);
    round_copy_kernel<<<(589824 / 4 + 255) / 256, 256>>>((const float4*)fc1_W, (float4*)(RW + OFF_FC1), 589824 / 4);
    round_copy_kernel<<<(196608 / 4 + 255) / 256, 256>>>((const float4*)r1_rt, (float4*)(RW + OFF_R1RT), 196608 / 4);
    round_copy_kernel<<<(393216 / 4 + 255) / 256, 256>>>((const float4*)r1_w,  (float4*)(RW + OFF_R1W),  393216 / 4);
    round_copy_kernel<<<(65536 / 4 + 255) / 256, 256>>>((const float4*)r2_rt, (float4*)(RW + OFF_R2RT), 65536 / 4);
    round_copy_kernel<<<(131072 / 4 + 255) / 256, 256>>>((const float4*)r2_w,  (float4*)(RW + OFF_R2W),  131072 / 4);
    round_copy_kernel<<<(65536 / 4 + 255) / 256, 256>>>((const float4*)fc2_W, (float4*)(RW + OFF_FC2), 65536 / 4);

    int mb = (Nn + 127) / 128;            // 391
    long long acc4 = (long long)Nn * 512 / 4;

    // ---- fc1: H1 = round(leaky(xr @ fc1_W + fc1_b)) ----
    mma_gemm_kernel<2, 1><<<dim3(mb, 6), 256, GEMM_SMEM>>>(T, RW + OFF_FC1, H1, fc1_b, Nn, DIN, DIN, DIN);

    // ---- layer-1 transforms into T (ldc=768) ----
    mma_gemm_kernel<1, 0><<<dim3(mb, 2), 256, GEMM_SMEM>>>(H1, RW + OFF_R1RT,              T,       r1_b,   Nn, DIN, DHID, 768);
    mma_gemm_kernel<0, 0><<<dim3(mb, 2), 256, GEMM_SMEM>>>(H1, RW + OFF_R1W,               T + 256, nullptr, Nn, DIN, DHID, 768);
    mma_gemm_kernel<0, 0><<<dim3(mb, 2), 256, GEMM_SMEM>>>(H1, RW + OFF_R1W + DIN * DHID,  T + 512, nullptr, Nn, DIN, DHID, 768);

    zero_f4_kernel<<<(unsigned)((acc4 + 255) / 256), 256>>>((float4*)ACC, acc4);
    scatter_kernel<<<(E + 7) / 8, 256>>>(ei32, ei64, et32, et64, T, ACC, E);
    normalize_kernel<<<(Nn * 64 + 255) / 256, 256>>>(T, ACC, CNT, X, Nn);

    // ---- layer-2 transforms ----
    mma_gemm_kernel<1, 0><<<dim3(mb, 2), 256, GEMM_SMEM>>>(X, RW + OFF_R2RT,               T,       r2_b,   Nn, DHID, DHID, 768);
    mma_gemm_kernel<0, 0><<<dim3(mb, 2), 256, GEMM_SMEM>>>(X, RW + OFF_R2W,                T + 256, nullptr, Nn, DHID, DHID, 768);
    mma_gemm_kernel<0, 0><<<dim3(mb, 2), 256, GEMM_SMEM>>>(X, RW + OFF_R2W + DHID * DHID,  T + 512, nullptr, Nn, DHID, DHID, 768);

    zero_f4_kernel<<<(unsigned)((acc4 + 255) / 256), 256>>>((float4*)ACC, acc4);
    scatter_kernel<<<(E + 7) / 8, 256>>>(ei32, ei64, et32, et64, T, ACC, E);
    normalize_kernel<<<(Nn * 64 + 255) / 256, 256>>>(T, ACC, CNT, X, Nn);

    // ---- fc2: F = leaky(X @ fc2_W + fc2_b) ----
    mma_gemm_kernel<2, 0><<<dim3(mb, 2), 256, GEMM_SMEM>>>(X, RW + OFF_FC2, F, fc2_b, Nn, DHID, DHID, DHID);

    // ---- head + softmax ----
    head_kernel<<<(Nn + 7) / 8, 256>>>(F, out_W, out_b, (float*)d_out, Nn);
}

// round 7
// speedup vs baseline: 3.3550x; 1.2788x over previous
#include <cuda_runtime.h>
#include <cstdint>
#include <math.h>

#define DIN  768
#define DHID 256
#define NREL 2
#define MAXN 50000
#define MAXE 800000

// ---------------- scratch (device globals) ------------------------------------
__device__ float g_H1[(size_t)MAXN * DIN];    // fc1 output [N,768] (tf32-rounded)
__device__ float g_T [(size_t)MAXN * 768];    // rounded x, then transforms [N,768]
__device__ float g_X [(size_t)MAXN * DHID];   // rgcn layer output [N,256] (rounded)
__device__ float g_F [(size_t)MAXN * DHID];   // fc2 output [N,256]
__device__ float g_RW[1441792];               // pre-rounded weights (concatenated)
__device__ float g_B1[768];
__device__ float g_B2[768];
__device__ int   g_CNT[MAXN * NREL];
__device__ int   g_OFF[MAXN * NREL];
__device__ int   g_CUR[MAXN * NREL];
__device__ int   g_SRC[MAXE];
__device__ int   g_TOTAL[1];
__device__ int   g_flag[1];

// offsets into g_RW (floats)
#define OFF_FC1   0
#define OFF_W1    589824        // WCAT1 [768 x 768]
#define OFF_W2    1179648       // WCAT2 [256 x 768]
#define OFF_FC2   1376256       // [256 x 256]

// ---------------- tf32 helpers ------------------------------------------------
__device__ __forceinline__ float tf32r(float f) {
    uint32_t r;
    asm("cvt.rna.tf32.f32 %0, %1;" : "=r"(r) : "f"(f));
    return __uint_as_float(r);
}
__device__ __forceinline__ void mma1688(float* c, const uint32_t* a, const uint32_t* b) {
    asm volatile("mma.sync.aligned.m16n8k8.row.col.f32.tf32.tf32.f32 "
                 "{%0,%1,%2,%3}, {%4,%5,%6,%7}, {%8,%9}, {%0,%1,%2,%3};"
                 : "+f"(c[0]), "+f"(c[1]), "+f"(c[2]), "+f"(c[3])
                 : "r"(a[0]), "r"(a[1]), "r"(a[2]), "r"(a[3]), "r"(b[0]), "r"(b[1]));
}
__device__ __forceinline__ void cpasync16(uint32_t saddr, const void* gptr, uint32_t sz) {
    asm volatile("cp.async.ca.shared.global [%0], [%1], 16, %2;"
                 :: "r"(saddr), "l"(gptr), "r"(sz) : "memory");
}
__device__ __forceinline__ uint32_t smem_u32(const void* p) {
    uint32_t a;
    asm("{ .reg .u64 t; cvta.to.shared.u64 t, %1; cvt.u32.u64 %0, t; }" : "=r"(a) : "l"(p));
    return a;
}

// ---------------- tf32 mma.sync GEMM, cp.async 4-stage pipeline ----------------
#define APAD 20
#define BPAD 136
#define STAGES 4
#define ASZ (128 * APAD)
#define BSZ (16 * BPAD)
#define GEMM_SMEM (STAGES * (ASZ + BSZ) * 4)

template<int EPI, int RND>  // EPI: 0 none, 1 +bias, 2 +bias+leaky; RND: round out to tf32
__global__ void __launch_bounds__(256, 2)
mma_gemm_kernel(const float* __restrict__ A, const float* __restrict__ B,
                float* __restrict__ C, const float* __restrict__ bias,
                int M, int K, int ldb, int ldc) {
    extern __shared__ float sm[];
    const uint32_t smem_base = smem_u32(sm);

    const int tid  = threadIdx.x;
    const int w    = tid >> 5;
    const int lane = tid & 31;
    const int g    = lane >> 2;
    const int cq   = lane & 3;
    const int wm   = w >> 2;
    const int wn   = w & 3;
    const int row0 = blockIdx.x * 128;
    const int col0 = blockIdx.y * 128;

    const int ar  = tid >> 2;
    const int ac4 = tid & 3;
    const int br  = tid >> 5;
    const int bc4 = tid & 31;
    const uint32_t aoff0 = (uint32_t)(ar * APAD + ac4 * 4) * 4;
    const uint32_t aoff1 = aoff0 + (uint32_t)(64 * APAD) * 4;
    const uint32_t boff0 = (uint32_t)(br * BPAD + bc4 * 4) * 4;
    const uint32_t boff1 = boff0 + (uint32_t)(8 * BPAD) * 4;

    const int gr0 = row0 + ar, gr1 = row0 + ar + 64;
    const uint32_t sz0 = (gr0 < M) ? 16u : 0u;
    const uint32_t sz1 = (gr1 < M) ? 16u : 0u;
    const float* agp0 = A + (size_t)(gr0 < M ? gr0 : 0) * K + ac4 * 4;
    const float* agp1 = A + (size_t)(gr1 < M ? gr1 : 0) * K + ac4 * 4;
    const float* bgp0 = B + (size_t)br * ldb + col0 + bc4 * 4;
    const float* bgp1 = bgp0 + (size_t)8 * ldb;
    const size_t bstep = (size_t)16 * ldb;

    const int nk = K >> 4;

    auto issue_stage = [&](int s, int t) {
        uint32_t abase = smem_base + (uint32_t)(s * ASZ) * 4;
        uint32_t bbase = smem_base + (uint32_t)(STAGES * ASZ + s * BSZ) * 4;
        cpasync16(abase + aoff0, agp0 + t * 16, sz0);
        cpasync16(abase + aoff1, agp1 + t * 16, sz1);
        cpasync16(bbase + boff0, bgp0 + (size_t)t * bstep, 16u);
        cpasync16(bbase + boff1, bgp1 + (size_t)t * bstep, 16u);
        asm volatile("cp.async.commit_group;" ::: "memory");
    };

    float acc[4][4][4];
    #pragma unroll
    for (int mi = 0; mi < 4; mi++)
        #pragma unroll
        for (int ni = 0; ni < 4; ni++)
            #pragma unroll
            for (int q = 0; q < 4; q++) acc[mi][ni][q] = 0.f;

    // prefetch depth 3
    issue_stage(0, 0);
    if (nk > 1) issue_stage(1, 1); else asm volatile("cp.async.commit_group;" ::: "memory");
    if (nk > 2) issue_stage(2, 2); else asm volatile("cp.async.commit_group;" ::: "memory");

    for (int t = 0; t < nk; t++) {
        if (t + 2 < nk)      { asm volatile("cp.async.wait_group 2;" ::: "memory"); }
        else if (t + 1 < nk) { asm volatile("cp.async.wait_group 1;" ::: "memory"); }
        else                 { asm volatile("cp.async.wait_group 0;" ::: "memory"); }
        __syncthreads();
        if (t + 3 < nk) issue_stage((t + 3) % STAGES, t + 3);

        const int s = t % STAGES;
        const float* As_st = sm + s * ASZ;
        const float* Bs_st = sm + STAGES * ASZ + s * BSZ;
        const int cbb = wn * 32 + g;

        #pragma unroll
        for (int k8 = 0; k8 < 2; k8++) {
            const int kc = k8 * 8 + cq;
            uint32_t af[4][4];
            #pragma unroll
            for (int mi = 0; mi < 4; mi++) {
                const float* ap = As_st + (wm * 64 + mi * 16 + g) * APAD;
                af[mi][0] = __float_as_uint(ap[kc]);
                af[mi][1] = __float_as_uint(ap[8 * APAD + kc]);
                af[mi][2] = __float_as_uint(ap[kc + 4]);
                af[mi][3] = __float_as_uint(ap[8 * APAD + kc + 4]);
            }
            uint32_t bf[4][2];
            const float* bp0r = Bs_st + kc * BPAD + cbb;
            const float* bp1r = bp0r + 4 * BPAD;
            #pragma unroll
            for (int ni = 0; ni < 4; ni++) {
                bf[ni][0] = __float_as_uint(bp0r[ni * 8]);
                bf[ni][1] = __float_as_uint(bp1r[ni * 8]);
            }
            #pragma unroll
            for (int mi = 0; mi < 4; mi++)
                #pragma unroll
                for (int ni = 0; ni < 4; ni++)
                    mma1688(acc[mi][ni], af[mi], bf[ni]);
        }
        __syncthreads();
    }

    #pragma unroll
    for (int mi = 0; mi < 4; mi++) {
        int rbase = row0 + wm * 64 + mi * 16;
        int r0 = rbase + g, r1 = rbase + g + 8;
        #pragma unroll
        for (int ni = 0; ni < 4; ni++) {
            int col = col0 + wn * 32 + ni * 8 + cq * 2;
            float b0 = 0.f, b1 = 0.f;
            if (EPI >= 1) { b0 = bias[col]; b1 = bias[col + 1]; }
            float v0 = acc[mi][ni][0] + b0, v1 = acc[mi][ni][1] + b1;
            float v2 = acc[mi][ni][2] + b0, v3 = acc[mi][ni][3] + b1;
            if (EPI == 2) {
                v0 = v0 >= 0.f ? v0 : 0.01f * v0;
                v1 = v1 >= 0.f ? v1 : 0.01f * v1;
                v2 = v2 >= 0.f ? v2 : 0.01f * v2;
                v3 = v3 >= 0.f ? v3 : 0.01f * v3;
            }
            if (RND) { v0 = tf32r(v0); v1 = tf32r(v1); v2 = tf32r(v2); v3 = tf32r(v3); }
            if (r0 < M) *(float2*)(C + (size_t)r0 * ldc + col) = make_float2(v0, v1);
            if (r1 < M) *(float2*)(C + (size_t)r1 * ldc + col) = make_float2(v2, v3);
        }
    }
}

// ---------------- pre-round copies --------------------------------------------
__global__ void round_copy_kernel(const float4* __restrict__ src, float4* __restrict__ dst,
                                  long long n4) {
    long long i = (long long)blockIdx.x * blockDim.x + threadIdx.x;
    if (i < n4) {
        float4 v = src[i];
        v.x = tf32r(v.x); v.y = tf32r(v.y); v.z = tf32r(v.z); v.w = tf32r(v.w);
        dst[i] = v;
    }
}
// copy [K x 256] block into wide [K x 768] buffer at given col offset (float4 units)
__global__ void round_block_kernel(const float4* __restrict__ src, float4* __restrict__ dst,
                                   int n4) {   // n4 = K*64; dst pre-offset to column
    int i = blockIdx.x * blockDim.x + threadIdx.x;
    if (i >= n4) return;
    int row = i >> 6, c = i & 63;
    float4 v = src[i];
    v.x = tf32r(v.x); v.y = tf32r(v.y); v.z = tf32r(v.z); v.w = tf32r(v.w);
    dst[row * 192 + c] = v;
}
__global__ void biascat_kernel(const float* __restrict__ b, float* __restrict__ out) {
    int i = blockIdx.x * blockDim.x + threadIdx.x;
    if (i < 768) out[i] = (i < 256) ? b[i] : 0.f;
}

// ---------------- edge machinery ----------------------------------------------
__global__ void probe_kernel(const long long* __restrict__ ei, long long Nn) {
    if (blockIdx.x == 0 && threadIdx.x == 0) {
        int ok = 1;
        for (int i = 0; i < 16; i++) {
            long long v = ei[i];
            if (v < 0 || v >= Nn) ok = 0;
        }
        g_flag[0] = ok;
        g_TOTAL[0] = 0;
    }
}
__global__ void zero_i_kernel(int* __restrict__ p, int n) {
    int i = blockIdx.x * blockDim.x + threadIdx.x;
    if (i < n) p[i] = 0;
}
__global__ void count_kernel(const int* __restrict__ ei32, const long long* __restrict__ ei64,
                             const int* __restrict__ et32, const long long* __restrict__ et64,
                             int* __restrict__ cnt, int E) {
    int e = blockIdx.x * blockDim.x + threadIdx.x;
    if (e >= E) return;
    long long dst; int r;
    if (g_flag[0]) { dst = ei64[(long long)E + e]; r = (int)et64[e]; }
    else           { dst = ei32[E + e];            r = et32[e]; }
    atomicAdd(&cnt[(int)dst * NREL + r], 1);
}
// block-scan with atomic block base (order-free, offsets just need uniqueness)
__global__ void scan_kernel(const int* __restrict__ cnt, int* __restrict__ off,
                            int* __restrict__ total, int n) {
    __shared__ int sh[256];
    __shared__ int base_sh;
    int i = blockIdx.x * 256 + threadIdx.x;
    int v = (i < n) ? cnt[i] : 0;
    sh[threadIdx.x] = v;
    __syncthreads();
    #pragma unroll
    for (int d = 1; d < 256; d <<= 1) {
        int t = (threadIdx.x >= d) ? sh[threadIdx.x - d] : 0;
        __syncthreads();
        sh[threadIdx.x] += t;
        __syncthreads();
    }
    if (threadIdx.x == 255) base_sh = atomicAdd(total, sh[255]);
    __syncthreads();
    if (i < n) off[i] = base_sh + sh[threadIdx.x] - v;
}
__global__ void copy_i_kernel(const int* __restrict__ s, int* __restrict__ d, int n) {
    int i = blockIdx.x * blockDim.x + threadIdx.x;
    if (i < n) d[i] = s[i];
}
__global__ void fill_kernel(const int* __restrict__ ei32, const long long* __restrict__ ei64,
                            const int* __restrict__ et32, const long long* __restrict__ et64,
                            int* __restrict__ cur, int* __restrict__ srcidx, int E) {
    int e = blockIdx.x * blockDim.x + threadIdx.x;
    if (e >= E) return;
    long long src, dst; int r;
    if (g_flag[0]) { src = ei64[e]; dst = ei64[(long long)E + e]; r = (int)et64[e]; }
    else           { src = ei32[e]; dst = ei32[E + e];            r = et32[e]; }
    int p = atomicAdd(&cur[(int)dst * NREL + r], 1);
    srcidx[p] = (int)src;
}

// ---------------- fused gather + mean + root + round --------------------------
// warp per node; lane covers 8 cols (2 float4); X = round(T_root + sum_r mean_r)
__global__ void gather_kernel(const int* __restrict__ srcidx, const int* __restrict__ off,
                              const int* __restrict__ cnt, const float* __restrict__ T,
                              float* __restrict__ X, int Nn) {
    int node = (blockIdx.x * blockDim.x + threadIdx.x) >> 5;
    int lane = threadIdx.x & 31;
    if (node >= Nn) return;

    float4 s[2][2];
    #pragma unroll
    for (int r = 0; r < 2; r++) { s[r][0] = make_float4(0,0,0,0); s[r][1] = make_float4(0,0,0,0); }

    #pragma unroll
    for (int r = 0; r < 2; r++) {
        const int base = off[node * 2 + r];
        const int n    = cnt[node * 2 + r];
        const size_t coloff = 256 + (size_t)r * 256;
        int e = 0;
        for (; e + 1 < n; e += 2) {
            int s0 = srcidx[base + e], s1 = srcidx[base + e + 1];
            const float4* p0 = (const float4*)(T + (size_t)s0 * 768 + coloff) + lane * 2;
            const float4* p1 = (const float4*)(T + (size_t)s1 * 768 + coloff) + lane * 2;
            float4 a0 = p0[0], a1 = p0[1], b0 = p1[0], b1 = p1[1];
            s[r][0].x += a0.x + b0.x; s[r][0].y += a0.y + b0.y;
            s[r][0].z += a0.z + b0.z; s[r][0].w += a0.w + b0.w;
            s[r][1].x += a1.x + b1.x; s[r][1].y += a1.y + b1.y;
            s[r][1].z += a1.z + b1.z; s[r][1].w += a1.w + b1.w;
        }
        if (e < n) {
            int s0 = srcidx[base + e];
            const float4* p0 = (const float4*)(T + (size_t)s0 * 768 + coloff) + lane * 2;
            float4 a0 = p0[0], a1 = p0[1];
            s[r][0].x += a0.x; s[r][0].y += a0.y; s[r][0].z += a0.z; s[r][0].w += a0.w;
            s[r][1].x += a1.x; s[r][1].y += a1.y; s[r][1].z += a1.z; s[r][1].w += a1.w;
        }
    }
    int c0 = cnt[node * 2], c1 = cnt[node * 2 + 1];
    float inv0 = 1.0f / (float)(c0 > 1 ? c0 : 1);
    float inv1 = 1.0f / (float)(c1 > 1 ? c1 : 1);
    const float4* tr = (const float4*)(T + (size_t)node * 768) + lane * 2;
    float4* xo = (float4*)(X + (size_t)node * DHID) + lane * 2;
    #pragma unroll
    for (int q = 0; q < 2; q++) {
        float4 t = tr[q];
        float4 o;
        o.x = tf32r(t.x + s[0][q].x * inv0 + s[1][q].x * inv1);
        o.y = tf32r(t.y + s[0][q].y * inv0 + s[1][q].y * inv1);
        o.z = tf32r(t.z + s[0][q].z * inv0 + s[1][q].z * inv1);
        o.w = tf32r(t.w + s[0][q].w * inv0 + s[1][q].w * inv1);
        xo[q] = o;
    }
}

// ---------------- head --------------------------------------------------------
__global__ void head_kernel(const float* __restrict__ H, const float* __restrict__ W,
                            const float* __restrict__ b, float* __restrict__ out, int Nn) {
    int w = (blockIdx.x * blockDim.x + threadIdx.x) >> 5;
    int lane = threadIdx.x & 31;
    if (w >= Nn) return;
    const float4* h = (const float4*)(H + (long long)w * DHID);
    float d0 = 0.f, d1 = 0.f;
    #pragma unroll
    for (int q = 0; q < 2; q++) {
        float4 hv = h[lane * 2 + q];
        int kbase = lane * 8 + q * 4;
        float4 w01 = ((const float4*)W)[kbase / 2];
        float4 w23 = ((const float4*)W)[kbase / 2 + 1];
        d0 += hv.x * w01.x + hv.y * w01.z + hv.z * w23.x + hv.w * w23.z;
        d1 += hv.x * w01.y + hv.y * w01.w + hv.z * w23.y + hv.w * w23.w;
    }
    #pragma unroll
    for (int off = 16; off > 0; off >>= 1) {
        d0 += __shfl_xor_sync(0xffffffffu, d0, off);
        d1 += __shfl_xor_sync(0xffffffffu, d1, off);
    }
    if (lane == 0) {
        d0 += b[0]; d1 += b[1];
        float m = fmaxf(d0, d1);
        float e0 = expf(d0 - m), e1 = expf(d1 - m);
        float s = e0 + e1;
        out[(long long)w * 2]     = e0 / s;
        out[(long long)w * 2 + 1] = e1 / s;
    }
}

// ---------------- launch ------------------------------------------------------
extern "C" void kernel_launch(void* const* d_in, const int* in_sizes, int n_in,
                              void* d_out, int out_size) {
    const float* x     = (const float*)d_in[0];
    const void*  ei    = d_in[1];
    const void*  et    = d_in[3];
    const float* fc1_W = (const float*)d_in[4];
    const float* fc1_b = (const float*)d_in[5];
    const float* r1_w  = (const float*)d_in[6];
    const float* r1_rt = (const float*)d_in[7];
    const float* r1_b  = (const float*)d_in[8];
    const float* r2_w  = (const float*)d_in[9];
    const float* r2_rt = (const float*)d_in[10];
    const float* r2_b  = (const float*)d_in[11];
    const float* fc2_W = (const float*)d_in[12];
    const float* fc2_b = (const float*)d_in[13];
    const float* out_W = (const float*)d_in[14];
    const float* out_b = (const float*)d_in[15];

    int Nn = in_sizes[0] / DIN;   // 50000
    int E  = in_sizes[3];         // 800000

    float *H1, *T, *X, *F, *RW, *B1, *B2;
    int *CNT, *OFF, *CUR, *SRC, *TOT;
    cudaGetSymbolAddress((void**)&H1,  g_H1);
    cudaGetSymbolAddress((void**)&T,   g_T);
    cudaGetSymbolAddress((void**)&X,   g_X);
    cudaGetSymbolAddress((void**)&F,   g_F);
    cudaGetSymbolAddress((void**)&RW,  g_RW);
    cudaGetSymbolAddress((void**)&B1,  g_B1);
    cudaGetSymbolAddress((void**)&B2,  g_B2);
    cudaGetSymbolAddress((void**)&CNT, g_CNT);
    cudaGetSymbolAddress((void**)&OFF, g_OFF);
    cudaGetSymbolAddress((void**)&CUR, g_CUR);
    cudaGetSymbolAddress((void**)&SRC, g_SRC);
    cudaGetSymbolAddress((void**)&TOT, g_TOTAL);

    cudaFuncSetAttribute(mma_gemm_kernel<2, 1>, cudaFuncAttributeMaxDynamicSharedMemorySize, GEMM_SMEM);
    cudaFuncSetAttribute(mma_gemm_kernel<1, 0>, cudaFuncAttributeMaxDynamicSharedMemorySize, GEMM_SMEM);
    cudaFuncSetAttribute(mma_gemm_kernel<2, 0>, cudaFuncAttributeMaxDynamicSharedMemorySize, GEMM_SMEM);

    const int*       ei32 = (const int*)ei;
    const long long* ei64 = (const long long*)ei;
    const int*       et32 = (const int*)et;
    const long long* et64 = (const long long*)et;

    int NC = Nn * NREL;   // 100000

    // ---- CSR build ----
    probe_kernel<<<1, 32>>>(ei64, (long long)Nn);
    zero_i_kernel<<<(NC + 255) / 256, 256>>>(CNT, NC);
    count_kernel<<<(E + 255) / 256, 256>>>(ei32, ei64, et32, et64, CNT, E);
    scan_kernel<<<(NC + 255) / 256, 256>>>(CNT, OFF, TOT, NC);
    copy_i_kernel<<<(NC + 255) / 256, 256>>>(OFF, CUR, NC);
    fill_kernel<<<(E + 255) / 256, 256>>>(ei32, ei64, et32, et64, CUR, SRC, E);

    // ---- pre-round x and weights (concatenated layouts) ----
    long long x4 = (long long)Nn * DIN / 4;
    round_copy_kernel<<<(unsigned)((x4 + 255) / 256), 256>>>((const float4*)x, (float4*)T, x4);
    round_copy_kernel<<<(589824 / 4 + 255) / 256, 256>>>((const float4*)fc1_W, (float4*)(RW + OFF_FC1), 589824 / 4);
    // WCAT1 [768 x 768]: cols 0-255 root, 256-511 W0, 512-767 W1
    round_block_kernel<<<(49152 + 255) / 256, 256>>>((const float4*)r1_rt,             (float4*)(RW + OFF_W1),       49152);
    round_block_kernel<<<(49152 + 255) / 256, 256>>>((const float4*)r1_w,              (float4*)(RW + OFF_W1 + 256), 49152);
    round_block_kernel<<<(49152 + 255) / 256, 256>>>((const float4*)(r1_w + DIN * DHID), (float4*)(RW + OFF_W1 + 512), 49152);
    // WCAT2 [256 x 768]
    round_block_kernel<<<(16384 + 255) / 256, 256>>>((const float4*)r2_rt,              (float4*)(RW + OFF_W2),       16384);
    round_block_kernel<<<(16384 + 255) / 256, 256>>>((const float4*)r2_w,               (float4*)(RW + OFF_W2 + 256), 16384);
    round_block_kernel<<<(16384 + 255) / 256, 256>>>((const float4*)(r2_w + DHID * DHID), (float4*)(RW + OFF_W2 + 512), 16384);
    round_copy_kernel<<<(65536 / 4 + 255) / 256, 256>>>((const float4*)fc2_W, (float4*)(RW + OFF_FC2), 65536 / 4);
    biascat_kernel<<<3, 256>>>(r1_b, B1);
    biascat_kernel<<<3, 256>>>(r2_b, B2);

    int mb = (Nn + 127) / 128;            // 391

    // ---- fc1: H1 = round(leaky(xr @ fc1_W + fc1_b)) ----
    mma_gemm_kernel<2, 1><<<dim3(mb, 6), 256, GEMM_SMEM>>>(T, RW + OFF_FC1, H1, fc1_b, Nn, DIN, DIN, DIN);

    // ---- layer-1: T = H1 @ WCAT1 (+bias on root cols) ----
    mma_gemm_kernel<1, 0><<<dim3(mb, 6), 256, GEMM_SMEM>>>(H1, RW + OFF_W1, T, B1, Nn, DIN, 768, 768);
    gather_kernel<<<(Nn + 7) / 8, 256>>>(SRC, OFF, CNT, T, X, Nn);

    // ---- layer-2: T = X @ WCAT2 (+bias on root cols) ----
    mma_gemm_kernel<1, 0><<<dim3(mb, 6), 256, GEMM_SMEM>>>(X, RW + OFF_W2, T, B2, Nn, DHID, 768, 768);
    gather_kernel<<<(Nn + 7) / 8, 256>>>(SRC, OFF, CNT, T, X, Nn);

    // ---- fc2: F = leaky(X @ fc2_W + fc2_b) ----
    mma_gemm_kernel<2, 0><<<dim3(mb, 2), 256, GEMM_SMEM>>>(X, RW + OFF_FC2, F, fc2_b, Nn, DHID, DHID, DHID);

    // ---- head + softmax ----
    head_kernel<<<(Nn + 7) / 8, 256>>>(F, out_W, out_b, (float*)d_out, Nn);
}

// round 8
// speedup vs baseline: 3.4545x; 1.0297x over previous
#include <cuda_runtime.h>
#include <cstdint>
#include <math.h>

#define DIN  768
#define DHID 256
#define NREL 2
#define MAXN 50000
#define MAXE 800000

// ---------------- scratch (device globals) ------------------------------------
__device__ float g_H1[(size_t)MAXN * DIN];    // fc1 output [N,768] (tf32-rounded)
__device__ float g_T [(size_t)MAXN * 768];    // rounded x, then transforms [N,768]
__device__ float g_X [(size_t)MAXN * DHID];   // rgcn layer output [N,256] (rounded)
__device__ float g_F [(size_t)MAXN * DHID];   // fc2 output [N,256]
__device__ float g_RW[1441792];               // pre-rounded weights (concatenated)
__device__ float g_B1[768];
__device__ float g_B2[768];
__device__ int   g_CNT[MAXN * NREL];
__device__ int   g_OFF[MAXN * NREL];
__device__ int   g_CUR[MAXN * NREL];
__device__ int   g_SRC[MAXE];
__device__ int   g_TOTAL[1];
__device__ int   g_flag[1];

// offsets into g_RW (floats)
#define OFF_FC1   0
#define OFF_W1    589824        // WCAT1 [768 x 768]
#define OFF_W2    1179648       // WCAT2 [256 x 768]
#define OFF_FC2   1376256       // [256 x 256]

// ---------------- tf32 helpers ------------------------------------------------
__device__ __forceinline__ float tf32r(float f) {
    uint32_t r;
    asm("cvt.rna.tf32.f32 %0, %1;" : "=r"(r) : "f"(f));
    return __uint_as_float(r);
}
__device__ __forceinline__ void mma1688(float* c, const uint32_t* a, const uint32_t* b) {
    asm volatile("mma.sync.aligned.m16n8k8.row.col.f32.tf32.tf32.f32 "
                 "{%0,%1,%2,%3}, {%4,%5,%6,%7}, {%8,%9}, {%0,%1,%2,%3};"
                 : "+f"(c[0]), "+f"(c[1]), "+f"(c[2]), "+f"(c[3])
                 : "r"(a[0]), "r"(a[1]), "r"(a[2]), "r"(a[3]), "r"(b[0]), "r"(b[1]));
}
__device__ __forceinline__ void cpasync16(uint32_t saddr, const void* gptr, uint32_t sz) {
    asm volatile("cp.async.ca.shared.global [%0], [%1], 16, %2;"
                 :: "r"(saddr), "l"(gptr), "r"(sz) : "memory");
}
__device__ __forceinline__ uint32_t smem_u32(const void* p) {
    uint32_t a;
    asm("{ .reg .u64 t; cvta.to.shared.u64 t, %1; cvt.u32.u64 %0, t; }" : "=r"(a) : "l"(p));
    return a;
}

// ---------------- tf32 mma.sync GEMM, cp.async 4-stage + ldmatrix A ------------
#define APAD 20
#define BPAD 136
#define STAGES 4
#define ASZ (128 * APAD)
#define BSZ (16 * BPAD)
#define GEMM_SMEM (STAGES * (ASZ + BSZ) * 4)

template<int EPI, int RND>  // EPI: 0 none, 1 +bias, 2 +bias+leaky; RND: round out to tf32
__global__ void __launch_bounds__(256, 2)
mma_gemm_kernel(const float* __restrict__ A, const float* __restrict__ B,
                float* __restrict__ C, const float* __restrict__ bias,
                int M, int K, int ldb, int ldc) {
    extern __shared__ float sm[];
    const uint32_t smem_base = smem_u32(sm);

    const int tid  = threadIdx.x;
    const int w    = tid >> 5;
    const int lane = tid & 31;
    const int g    = lane >> 2;
    const int cq   = lane & 3;
    const int wm   = w >> 2;
    const int wn   = w & 3;
    const int row0 = blockIdx.x * 128;
    const int col0 = blockIdx.y * 128;

    const int ar  = tid >> 2;
    const int ac4 = tid & 3;
    const int br  = tid >> 5;
    const int bc4 = tid & 31;
    const uint32_t aoff0 = (uint32_t)(ar * APAD + ac4 * 4) * 4;
    const uint32_t aoff1 = aoff0 + (uint32_t)(64 * APAD) * 4;
    const uint32_t boff0 = (uint32_t)(br * BPAD + bc4 * 4) * 4;
    const uint32_t boff1 = boff0 + (uint32_t)(8 * BPAD) * 4;

    const int gr0 = row0 + ar, gr1 = row0 + ar + 64;
    const uint32_t sz0 = (gr0 < M) ? 16u : 0u;
    const uint32_t sz1 = (gr1 < M) ? 16u : 0u;
    const float* agp0 = A + (size_t)(gr0 < M ? gr0 : 0) * K + ac4 * 4;
    const float* agp1 = A + (size_t)(gr1 < M ? gr1 : 0) * K + ac4 * 4;
    const float* bgp0 = B + (size_t)br * ldb + col0 + bc4 * 4;
    const float* bgp1 = bgp0 + (size_t)8 * ldb;
    const size_t bstep = (size_t)16 * ldb;

    // ldmatrix per-lane address offset (floats): matrix = lane>>3
    //   m0: rows+0 k+0 | m1: rows+8 k+0 | m2: rows+0 k+4 | m3: rows+8 k+4
    const int lm_mat  = lane >> 3;
    const int lm_row  = (lane & 7) + ((lm_mat & 1) << 3);
    const int lm_koff = (lm_mat >> 1) * 4;
    const uint32_t a_lm_off = (uint32_t)((wm * 64 + lm_row) * APAD + lm_koff) * 4;

    const int nk = K >> 4;

    auto issue_stage = [&](int s, int t) {
        uint32_t abase = smem_base + (uint32_t)(s * ASZ) * 4;
        uint32_t bbase = smem_base + (uint32_t)(STAGES * ASZ + s * BSZ) * 4;
        cpasync16(abase + aoff0, agp0 + t * 16, sz0);
        cpasync16(abase + aoff1, agp1 + t * 16, sz1);
        cpasync16(bbase + boff0, bgp0 + (size_t)t * bstep, 16u);
        cpasync16(bbase + boff1, bgp1 + (size_t)t * bstep, 16u);
        asm volatile("cp.async.commit_group;" ::: "memory");
    };

    float acc[4][4][4];
    #pragma unroll
    for (int mi = 0; mi < 4; mi++)
        #pragma unroll
        for (int ni = 0; ni < 4; ni++)
            #pragma unroll
            for (int q = 0; q < 4; q++) acc[mi][ni][q] = 0.f;

    issue_stage(0, 0);
    if (nk > 1) issue_stage(1, 1); else asm volatile("cp.async.commit_group;" ::: "memory");
    if (nk > 2) issue_stage(2, 2); else asm volatile("cp.async.commit_group;" ::: "memory");

    for (int t = 0; t < nk; t++) {
        if (t + 2 < nk)      { asm volatile("cp.async.wait_group 2;" ::: "memory"); }
        else if (t + 1 < nk) { asm volatile("cp.async.wait_group 1;" ::: "memory"); }
        else                 { asm volatile("cp.async.wait_group 0;" ::: "memory"); }
        __syncthreads();
        if (t + 3 < nk) issue_stage((t + 3) % STAGES, t + 3);

        const int s = t % STAGES;
        const uint32_t aS = smem_base + (uint32_t)(s * ASZ) * 4;
        const float* Bs_st = sm + STAGES * ASZ + s * BSZ;
        const int cbb = wn * 32 + g;

        #pragma unroll
        for (int k8 = 0; k8 < 2; k8++) {
            const int kc = k8 * 8 + cq;
            uint32_t af[4][4];
            #pragma unroll
            for (int mi = 0; mi < 4; mi++) {
                uint32_t addr = aS + a_lm_off + (uint32_t)(mi * 16 * APAD + k8 * 8) * 4;
                asm volatile("ldmatrix.sync.aligned.m8n8.x4.shared.b16 {%0,%1,%2,%3}, [%4];"
                    : "=r"(af[mi][0]), "=r"(af[mi][1]), "=r"(af[mi][2]), "=r"(af[mi][3])
                    : "r"(addr));
            }
            uint32_t bf[4][2];
            const float* bp0r = Bs_st + kc * BPAD + cbb;
            const float* bp1r = bp0r + 4 * BPAD;
            #pragma unroll
            for (int ni = 0; ni < 4; ni++) {
                bf[ni][0] = __float_as_uint(bp0r[ni * 8]);
                bf[ni][1] = __float_as_uint(bp1r[ni * 8]);
            }
            #pragma unroll
            for (int mi = 0; mi < 4; mi++)
                #pragma unroll
                for (int ni = 0; ni < 4; ni++)
                    mma1688(acc[mi][ni], af[mi], bf[ni]);
        }
        __syncthreads();
    }

    #pragma unroll
    for (int mi = 0; mi < 4; mi++) {
        int rbase = row0 + wm * 64 + mi * 16;
        int r0 = rbase + g, r1 = rbase + g + 8;
        #pragma unroll
        for (int ni = 0; ni < 4; ni++) {
            int col = col0 + wn * 32 + ni * 8 + cq * 2;
            float b0 = 0.f, b1 = 0.f;
            if (EPI >= 1) { b0 = bias[col]; b1 = bias[col + 1]; }
            float v0 = acc[mi][ni][0] + b0, v1 = acc[mi][ni][1] + b1;
            float v2 = acc[mi][ni][2] + b0, v3 = acc[mi][ni][3] + b1;
            if (EPI == 2) {
                v0 = v0 >= 0.f ? v0 : 0.01f * v0;
                v1 = v1 >= 0.f ? v1 : 0.01f * v1;
                v2 = v2 >= 0.f ? v2 : 0.01f * v2;
                v3 = v3 >= 0.f ? v3 : 0.01f * v3;
            }
            if (RND) { v0 = tf32r(v0); v1 = tf32r(v1); v2 = tf32r(v2); v3 = tf32r(v3); }
            if (r0 < M) *(float2*)(C + (size_t)r0 * ldc + col) = make_float2(v0, v1);
            if (r1 < M) *(float2*)(C + (size_t)r1 * ldc + col) = make_float2(v2, v3);
        }
    }
}

// ---------------- pre-round copies --------------------------------------------
__global__ void round_copy_kernel(const float4* __restrict__ src, float4* __restrict__ dst,
                                  long long n4) {
    long long i = (long long)blockIdx.x * blockDim.x + threadIdx.x;
    if (i < n4) {
        float4 v = src[i];
        v.x = tf32r(v.x); v.y = tf32r(v.y); v.z = tf32r(v.z); v.w = tf32r(v.w);
        dst[i] = v;
    }
}
__global__ void round_block_kernel(const float4* __restrict__ src, float4* __restrict__ dst,
                                   int n4) {
    int i = blockIdx.x * blockDim.x + threadIdx.x;
    if (i >= n4) return;
    int row = i >> 6, c = i & 63;
    float4 v = src[i];
    v.x = tf32r(v.x); v.y = tf32r(v.y); v.z = tf32r(v.z); v.w = tf32r(v.w);
    dst[row * 192 + c] = v;
}
__global__ void biascat_kernel(const float* __restrict__ b, float* __restrict__ out) {
    int i = blockIdx.x * blockDim.x + threadIdx.x;
    if (i < 768) out[i] = (i < 256) ? b[i] : 0.f;
}

// ---------------- edge machinery ----------------------------------------------
__global__ void probe_kernel(const long long* __restrict__ ei, long long Nn) {
    if (blockIdx.x == 0 && threadIdx.x == 0) {
        int ok = 1;
        for (int i = 0; i < 16; i++) {
            long long v = ei[i];
            if (v < 0 || v >= Nn) ok = 0;
        }
        g_flag[0] = ok;
        g_TOTAL[0] = 0;
    }
}
__global__ void zero_i_kernel(int* __restrict__ p, int n) {
    int i = blockIdx.x * blockDim.x + threadIdx.x;
    if (i < n) p[i] = 0;
}
__global__ void count_kernel(const int* __restrict__ ei32, const long long* __restrict__ ei64,
                             const int* __restrict__ et32, const long long* __restrict__ et64,
                             int* __restrict__ cnt, int E) {
    int e = blockIdx.x * blockDim.x + threadIdx.x;
    if (e >= E) return;
    long long dst; int r;
    if (g_flag[0]) { dst = ei64[(long long)E + e]; r = (int)et64[e]; }
    else           { dst = ei32[E + e];            r = et32[e]; }
    atomicAdd(&cnt[(int)dst * NREL + r], 1);
}
__global__ void scan_kernel(const int* __restrict__ cnt, int* __restrict__ off,
                            int* __restrict__ total, int n) {
    __shared__ int sh[256];
    __shared__ int base_sh;
    int i = blockIdx.x * 256 + threadIdx.x;
    int v = (i < n) ? cnt[i] : 0;
    sh[threadIdx.x] = v;
    __syncthreads();
    #pragma unroll
    for (int d = 1; d < 256; d <<= 1) {
        int t = (threadIdx.x >= d) ? sh[threadIdx.x - d] : 0;
        __syncthreads();
        sh[threadIdx.x] += t;
        __syncthreads();
    }
    if (threadIdx.x == 255) base_sh = atomicAdd(total, sh[255]);
    __syncthreads();
    if (i < n) off[i] = base_sh + sh[threadIdx.x] - v;
}
__global__ void copy_i_kernel(const int* __restrict__ s, int* __restrict__ d, int n) {
    int i = blockIdx.x * blockDim.x + threadIdx.x;
    if (i < n) d[i] = s[i];
}
__global__ void fill_kernel(const int* __restrict__ ei32, const long long* __restrict__ ei64,
                            const int* __restrict__ et32, const long long* __restrict__ et64,
                            int* __restrict__ cur, int* __restrict__ srcidx, int E) {
    int e = blockIdx.x * blockDim.x + threadIdx.x;
    if (e >= E) return;
    long long src, dst; int r;
    if (g_flag[0]) { src = ei64[e]; dst = ei64[(long long)E + e]; r = (int)et64[e]; }
    else           { src = ei32[e]; dst = ei32[E + e];            r = et32[e]; }
    int p = atomicAdd(&cur[(int)dst * NREL + r], 1);
    srcidx[p] = (int)src;
}

// ---------------- fused gather + mean + root + round --------------------------
__global__ void gather_kernel(const int* __restrict__ srcidx, const int* __restrict__ off,
                              const int* __restrict__ cnt, const float* __restrict__ T,
                              float* __restrict__ X, int Nn) {
    int node = (blockIdx.x * blockDim.x + threadIdx.x) >> 5;
    int lane = threadIdx.x & 31;
    if (node >= Nn) return;

    float4 s[2][2];
    #pragma unroll
    for (int r = 0; r < 2; r++) { s[r][0] = make_float4(0,0,0,0); s[r][1] = make_float4(0,0,0,0); }

    #pragma unroll
    for (int r = 0; r < 2; r++) {
        const int base = off[node * 2 + r];
        const int n    = cnt[node * 2 + r];
        const size_t coloff = 256 + (size_t)r * 256;
        int e = 0;
        for (; e + 1 < n; e += 2) {
            int s0 = srcidx[base + e], s1 = srcidx[base + e + 1];
            const float4* p0 = (const float4*)(T + (size_t)s0 * 768 + coloff) + lane * 2;
            const float4* p1 = (const float4*)(T + (size_t)s1 * 768 + coloff) + lane * 2;
            float4 a0 = p0[0], a1 = p0[1], b0 = p1[0], b1 = p1[1];
            s[r][0].x += a0.x + b0.x; s[r][0].y += a0.y + b0.y;
            s[r][0].z += a0.z + b0.z; s[r][0].w += a0.w + b0.w;
            s[r][1].x += a1.x + b1.x; s[r][1].y += a1.y + b1.y;
            s[r][1].z += a1.z + b1.z; s[r][1].w += a1.w + b1.w;
        }
        if (e < n) {
            int s0 = srcidx[base + e];
            const float4* p0 = (const float4*)(T + (size_t)s0 * 768 + coloff) + lane * 2;
            float4 a0 = p0[0], a1 = p0[1];
            s[r][0].x += a0.x; s[r][0].y += a0.y; s[r][0].z += a0.z; s[r][0].w += a0.w;
            s[r][1].x += a1.x; s[r][1].y += a1.y; s[r][1].z += a1.z; s[r][1].w += a1.w;
        }
    }
    int c0 = cnt[node * 2], c1 = cnt[node * 2 + 1];
    float inv0 = 1.0f / (float)(c0 > 1 ? c0 : 1);
    float inv1 = 1.0f / (float)(c1 > 1 ? c1 : 1);
    const float4* tr = (const float4*)(T + (size_t)node * 768) + lane * 2;
    float4* xo = (float4*)(X + (size_t)node * DHID) + lane * 2;
    #pragma unroll
    for (int q = 0; q < 2; q++) {
        float4 t = tr[q];
        float4 o;
        o.x = tf32r(t.x + s[0][q].x * inv0 + s[1][q].x * inv1);
        o.y = tf32r(t.y + s[0][q].y * inv0 + s[1][q].y * inv1);
        o.z = tf32r(t.z + s[0][q].z * inv0 + s[1][q].z * inv1);
        o.w = tf32r(t.w + s[0][q].w * inv0 + s[1][q].w * inv1);
        xo[q] = o;
    }
}

// ---------------- head --------------------------------------------------------
__global__ void head_kernel(const float* __restrict__ H, const float* __restrict__ W,
                            const float* __restrict__ b, float* __restrict__ out, int Nn) {
    int w = (blockIdx.x * blockDim.x + threadIdx.x) >> 5;
    int lane = threadIdx.x & 31;
    if (w >= Nn) return;
    const float4* h = (const float4*)(H + (long long)w * DHID);
    float d0 = 0.f, d1 = 0.f;
    #pragma unroll
    for (int q = 0; q < 2; q++) {
        float4 hv = h[lane * 2 + q];
        int kbase = lane * 8 + q * 4;
        float4 w01 = ((const float4*)W)[kbase / 2];
        float4 w23 = ((const float4*)W)[kbase / 2 + 1];
        d0 += hv.x * w01.x + hv.y * w01.z + hv.z * w23.x + hv.w * w23.z;
        d1 += hv.x * w01.y + hv.y * w01.w + hv.z * w23.y + hv.w * w23.w;
    }
    #pragma unroll
    for (int off = 16; off > 0; off >>= 1) {
        d0 += __shfl_xor_sync(0xffffffffu, d0, off);
        d1 += __shfl_xor_sync(0xffffffffu, d1, off);
    }
    if (lane == 0) {
        d0 += b[0]; d1 += b[1];
        float m = fmaxf(d0, d1);
        float e0 = expf(d0 - m), e1 = expf(d1 - m);
        float s = e0 + e1;
        out[(long long)w * 2]     = e0 / s;
        out[(long long)w * 2 + 1] = e1 / s;
    }
}

// ---------------- launch ------------------------------------------------------
extern "C" void kernel_launch(void* const* d_in, const int* in_sizes, int n_in,
                              void* d_out, int out_size) {
    const float* x     = (const float*)d_in[0];
    const void*  ei    = d_in[1];
    const void*  et    = d_in[3];
    const float* fc1_W = (const float*)d_in[4];
    const float* fc1_b = (const float*)d_in[5];
    const float* r1_w  = (const float*)d_in[6];
    const float* r1_rt = (const float*)d_in[7];
    const float* r1_b  = (const float*)d_in[8];
    const float* r2_w  = (const float*)d_in[9];
    const float* r2_rt = (const float*)d_in[10];
    const float* r2_b  = (const float*)d_in[11];
    const float* fc2_W = (const float*)d_in[12];
    const float* fc2_b = (const float*)d_in[13];
    const float* out_W = (const float*)d_in[14];
    const float* out_b = (const float*)d_in[15];

    int Nn = in_sizes[0] / DIN;   // 50000
    int E  = in_sizes[3];         // 800000

    float *H1, *T, *X, *F, *RW, *B1, *B2;
    int *CNT, *OFF, *CUR, *SRC, *TOT;
    cudaGetSymbolAddress((void**)&H1,  g_H1);
    cudaGetSymbolAddress((void**)&T,   g_T);
    cudaGetSymbolAddress((void**)&X,   g_X);
    cudaGetSymbolAddress((void**)&F,   g_F);
    cudaGetSymbolAddress((void**)&RW,  g_RW);
    cudaGetSymbolAddress((void**)&B1,  g_B1);
    cudaGetSymbolAddress((void**)&B2,  g_B2);
    cudaGetSymbolAddress((void**)&CNT, g_CNT);
    cudaGetSymbolAddress((void**)&OFF, g_OFF);
    cudaGetSymbolAddress((void**)&CUR, g_CUR);
    cudaGetSymbolAddress((void**)&SRC, g_SRC);
    cudaGetSymbolAddress((void**)&TOT, g_TOTAL);

    cudaFuncSetAttribute(mma_gemm_kernel<2, 1>, cudaFuncAttributeMaxDynamicSharedMemorySize, GEMM_SMEM);
    cudaFuncSetAttribute(mma_gemm_kernel<1, 0>, cudaFuncAttributeMaxDynamicSharedMemorySize, GEMM_SMEM);
    cudaFuncSetAttribute(mma_gemm_kernel<2, 0>, cudaFuncAttributeMaxDynamicSharedMemorySize, GEMM_SMEM);

    const int*       ei32 = (const int*)ei;
    const long long* ei64 = (const long long*)ei;
    const int*       et32 = (const int*)et;
    const long long* et64 = (const long long*)et;

    int NC = Nn * NREL;   // 100000

    // ---- CSR build ----
    probe_kernel<<<1, 32>>>(ei64, (long long)Nn);
    zero_i_kernel<<<(NC + 255) / 256, 256>>>(CNT, NC);
    count_kernel<<<(E + 255) / 256, 256>>>(ei32, ei64, et32, et64, CNT, E);
    scan_kernel<<<(NC + 255) / 256, 256>>>(CNT, OFF, TOT, NC);
    copy_i_kernel<<<(NC + 255) / 256, 256>>>(OFF, CUR, NC);
    fill_kernel<<<(E + 255) / 256, 256>>>(ei32, ei64, et32, et64, CUR, SRC, E);

    // ---- pre-round x and weights (concatenated layouts) ----
    long long x4 = (long long)Nn * DIN / 4;
    round_copy_kernel<<<(unsigned)((x4 + 255) / 256), 256>>>((const float4*)x, (float4*)T, x4);
    round_copy_kernel<<<(589824 / 4 + 255) / 256, 256>>>((const float4*)fc1_W, (float4*)(RW + OFF_FC1), 589824 / 4);
    round_block_kernel<<<(49152 + 255) / 256, 256>>>((const float4*)r1_rt,               (float4*)(RW + OFF_W1),       49152);
    round_block_kernel<<<(49152 + 255) / 256, 256>>>((const float4*)r1_w,                (float4*)(RW + OFF_W1 + 256), 49152);
    round_block_kernel<<<(49152 + 255) / 256, 256>>>((const float4*)(r1_w + DIN * DHID), (float4*)(RW + OFF_W1 + 512), 49152);
    round_block_kernel<<<(16384 + 255) / 256, 256>>>((const float4*)r2_rt,               (float4*)(RW + OFF_W2),       16384);
    round_block_kernel<<<(16384 + 255) / 256, 256>>>((const float4*)r2_w,                (float4*)(RW + OFF_W2 + 256), 16384);
    round_block_kernel<<<(16384 + 255) / 256, 256>>>((const float4*)(r2_w + DHID * DHID),(float4*)(RW + OFF_W2 + 512), 16384);
    round_copy_kernel<<<(65536 / 4 + 255) / 256, 256>>>((const float4*)fc2_W, (float4*)(RW + OFF_FC2), 65536 / 4);
    biascat_kernel<<<3, 256>>>(r1_b, B1);
    biascat_kernel<<<3, 256>>>(r2_b, B2);

    int mb = (Nn + 127) / 128;            // 391

    // ---- fc1: H1 = round(leaky(xr @ fc1_W + fc1_b)) ----
    mma_gemm_kernel<2, 1><<<dim3(mb, 6), 256, GEMM_SMEM>>>(T, RW + OFF_FC1, H1, fc1_b, Nn, DIN, DIN, DIN);

    // ---- layer-1: T = H1 @ WCAT1 (+bias on root cols) ----
    mma_gemm_kernel<1, 0><<<dim3(mb, 6), 256, GEMM_SMEM>>>(H1, RW + OFF_W1, T, B1, Nn, DIN, 768, 768);
    gather_kernel<<<(Nn + 7) / 8, 256>>>(SRC, OFF, CNT, T, X, Nn);

    // ---- layer-2: T = X @ WCAT2 (+bias on root cols) ----
    mma_gemm_kernel<1, 0><<<dim3(mb, 6), 256, GEMM_SMEM>>>(X, RW + OFF_W2, T, B2, Nn, DHID, 768, 768);
    gather_kernel<<<(Nn + 7) / 8, 256>>>(SRC, OFF, CNT, T, X, Nn);

    // ---- fc2: F = leaky(X @ fc2_W + fc2_b) ----
    mma_gemm_kernel<2, 0><<<dim3(mb, 2), 256, GEMM_SMEM>>>(X, RW + OFF_FC2, F, fc2_b, Nn, DHID, DHID, DHID);

    // ---- head + softmax ----
    head_kernel<<<(Nn + 7) / 8, 256>>>(F, out_W, out_b, (float*)d_out, Nn);
}